// round 6
// baseline (speedup 1.0000x reference)
#include <cuda_runtime.h>
#include <cuda_fp16.h>
#include <cstdint>

#define N_NODES 100000
#define E_EDGES 1600000
#define SCAN_CHUNK 1024
#define NB_SCAN ((N_NODES + SCAN_CHUNK - 1) / SCAN_CHUNK)   // 98

// ---------------- scratch (device globals; no allocation allowed) -------------
__device__ int    g_deg_src[N_NODES];
__device__ int    g_deg_dst[N_NODES];
__device__ int    g_cursor[N_NODES];
__device__ int    g_row_start[N_NODES + 1];
__device__ int    g_blockSums[NB_SCAN];
__device__ int    g_blockOff[NB_SCAN];
__device__ int    g_csr_src[E_EDGES];
__device__ int    g_maxdeg;
__device__ float  g_scale;
__device__ float  g_bufP0[(size_t)N_NODES * 64];
__device__ float  g_bufP1[(size_t)N_NODES * 64];
__device__ __half g_bufZ0[(size_t)N_NODES * 64];
__device__ __half g_bufZ1[(size_t)N_NODES * 64];

// ---------------- packed fp32x2 helpers ---------------------------------------
__device__ __forceinline__ unsigned long long pack2(float a, float b) {
    unsigned long long r;
    asm("mov.b64 %0, {%1, %2};" : "=l"(r) : "f"(a), "f"(b));
    return r;
}
__device__ __forceinline__ void unpack2(unsigned long long p, float& a, float& b) {
    asm("mov.b64 {%0, %1}, %2;" : "=f"(a), "=f"(b) : "l"(p));
}
__device__ __forceinline__ void ffma2(unsigned long long& d,
                                      unsigned long long a, unsigned long long b) {
    asm("fma.rn.f32x2 %0, %1, %2, %0;" : "+l"(d) : "l"(a), "l"(b));
}

// ---------------- prologue: degrees, max, scan, CSR fill ----------------------
__global__ void k_init()
{
    int i = blockIdx.x * blockDim.x + threadIdx.x;
    if (i < N_NODES) { g_deg_src[i] = 0; g_deg_dst[i] = 0; }
    if (i == 0) g_maxdeg = 0;
}

__global__ void k_deg(const int* __restrict__ esrc, const int* __restrict__ edst)
{
    int e = blockIdx.x * blockDim.x + threadIdx.x;
    if (e < E_EDGES) {
        atomicAdd(&g_deg_src[esrc[e]], 1);
        atomicAdd(&g_deg_dst[edst[e]], 1);
    }
}

// exclusive scan of deg_dst (chunk pass) + max-reduce of deg_src
__global__ __launch_bounds__(256) void k_scan1()
{
    __shared__ int warp_tot[8];
    __shared__ int warp_max[8];
    int b = blockIdx.x, t = threadIdx.x;
    int base = b * SCAN_CHUNK + t * 4;
    int v0 = (base + 0 < N_NODES) ? g_deg_dst[base + 0] : 0;
    int v1 = (base + 1 < N_NODES) ? g_deg_dst[base + 1] : 0;
    int v2 = (base + 2 < N_NODES) ? g_deg_dst[base + 2] : 0;
    int v3 = (base + 3 < N_NODES) ? g_deg_dst[base + 3] : 0;
    int m0 = (base + 0 < N_NODES) ? g_deg_src[base + 0] : 0;
    int m1 = (base + 1 < N_NODES) ? g_deg_src[base + 1] : 0;
    int m2 = (base + 2 < N_NODES) ? g_deg_src[base + 2] : 0;
    int m3 = (base + 3 < N_NODES) ? g_deg_src[base + 3] : 0;
    int s1 = v0, s2 = s1 + v1, s3 = s2 + v2, tot = s3 + v3;
    int mx = max(max(m0, m1), max(m2, m3));

    int lane = t & 31, w = t >> 5;
    int inc = tot;
    #pragma unroll
    for (int o = 1; o < 32; o <<= 1) {
        int n = __shfl_up_sync(0xFFFFFFFFu, inc, o);
        if (lane >= o) inc += n;
    }
    #pragma unroll
    for (int o = 16; o; o >>= 1) mx = max(mx, __shfl_xor_sync(0xFFFFFFFFu, mx, o));
    if (lane == 31) warp_tot[w] = inc;
    if (lane == 0)  warp_max[w] = mx;
    __syncthreads();
    if (t == 0) {
        int run = 0, bm = 0;
        #pragma unroll
        for (int i = 0; i < 8; i++) {
            int x = warp_tot[i]; warp_tot[i] = run; run += x;
            bm = max(bm, warp_max[i]);
        }
        g_blockSums[b] = run;
        atomicMax(&g_maxdeg, bm);
    }
    __syncthreads();
    int excl = warp_tot[w] + (inc - tot);
    if (base + 0 < N_NODES) g_row_start[base + 0] = excl;
    if (base + 1 < N_NODES) g_row_start[base + 1] = excl + s1;
    if (base + 2 < N_NODES) g_row_start[base + 2] = excl + s2;
    if (base + 3 < N_NODES) g_row_start[base + 3] = excl + s3;
}

__global__ void k_scan2()
{
    int run = 0;
    for (int b = 0; b < NB_SCAN; b++) { g_blockOff[b] = run; run += g_blockSums[b]; }
    g_scale = 1.0f / (float)max(g_maxdeg, 1);
}

__global__ void k_scan3()
{
    int i = blockIdx.x * blockDim.x + threadIdx.x;
    if (i < N_NODES) {
        int rs = g_row_start[i] + g_blockOff[i >> 10];
        g_row_start[i] = rs;
        g_cursor[i] = rs;
    }
    if (i == 0) g_row_start[N_NODES] = E_EDGES;
}

__global__ void k_fill(const int* __restrict__ esrc, const int* __restrict__ edst)
{
    int e = blockIdx.x * blockDim.x + threadIdx.x;
    if (e < E_EDGES) {
        int d = edst[e];
        int pos = atomicAdd(&g_cursor[d], 1);
        g_csr_src[pos] = esrc[e];
    }
}

// ---------------- fused [gather +] dual GEMM (FFMA2) --------------------------
// Input row i (64 ch):
//   GATHER=false: h = H[i]                       (layer 0, raw x)
//   GATHER=true : h = relu(P0p[i] + sum_{e in in(i)} Zp[src_e])
// Outputs: P0[i,c] = (h@W0)[i,c] + b[c] + norm_loop[i]*z[i,c]
//          Zh[i,c] = fp16(-scale * z[i,c]),  z = h@W1
template<int COUT, bool GATHER>
__global__ __launch_bounds__(256, 3)
void cheb_gemm(const float* __restrict__ H,
               const float* __restrict__ P0p,
               const __half* __restrict__ Zp,
               const float* __restrict__ W0,
               const float* __restrict__ W1,
               const float* __restrict__ B,
               float* __restrict__ P0,
               __half* __restrict__ Zh)
{
    __shared__ float sh[64][68];
    __shared__ float sw0[64][64];
    __shared__ float sw1[64][64];

    const int t    = threadIdx.x;
    const int row0 = blockIdx.x * 64;
    const int lane = t & 31, w = t >> 5;

    // weights (zero-pad cols >= COUT)
    for (int i = t; i < 64 * 64; i += 256) {
        int k = i >> 6, c = i & 63;
        float a = 0.f, bb = 0.f;
        if (c < COUT) { a = W0[k * COUT + c]; bb = W1[k * COUT + c]; }
        sw0[k][c] = a;
        sw1[k][c] = bb;
    }

    if (GATHER) {
        // warp w gathers rows w*8 .. w*8+7; lane handles channels 2*lane, 2*lane+1
        const __half2* Z2 = reinterpret_cast<const __half2*>(Zp);
        #pragma unroll
        for (int rr = 0; rr < 8; rr++) {
            int rloc = w * 8 + rr;
            int gr = row0 + rloc;
            float2 acc = make_float2(0.f, 0.f);
            if (gr < N_NODES) {
                acc = __ldg(reinterpret_cast<const float2*>(P0p + (size_t)gr * 64) + lane);
                int e   = g_row_start[gr];
                int end = g_row_start[gr + 1];
                for (; e + 8 <= end; e += 8) {
                    int s0 = __ldg(&g_csr_src[e + 0]);
                    int s1 = __ldg(&g_csr_src[e + 1]);
                    int s2 = __ldg(&g_csr_src[e + 2]);
                    int s3 = __ldg(&g_csr_src[e + 3]);
                    int s4 = __ldg(&g_csr_src[e + 4]);
                    int s5 = __ldg(&g_csr_src[e + 5]);
                    int s6 = __ldg(&g_csr_src[e + 6]);
                    int s7 = __ldg(&g_csr_src[e + 7]);
                    float2 f0 = __half22float2(__ldg(Z2 + s0 * 32 + lane));
                    float2 f1 = __half22float2(__ldg(Z2 + s1 * 32 + lane));
                    float2 f2 = __half22float2(__ldg(Z2 + s2 * 32 + lane));
                    float2 f3 = __half22float2(__ldg(Z2 + s3 * 32 + lane));
                    float2 f4 = __half22float2(__ldg(Z2 + s4 * 32 + lane));
                    float2 f5 = __half22float2(__ldg(Z2 + s5 * 32 + lane));
                    float2 f6 = __half22float2(__ldg(Z2 + s6 * 32 + lane));
                    float2 f7 = __half22float2(__ldg(Z2 + s7 * 32 + lane));
                    acc.x += ((f0.x + f1.x) + (f2.x + f3.x)) + ((f4.x + f5.x) + (f6.x + f7.x));
                    acc.y += ((f0.y + f1.y) + (f2.y + f3.y)) + ((f4.y + f5.y) + (f6.y + f7.y));
                }
                for (; e < end; e++) {
                    int s = __ldg(&g_csr_src[e]);
                    float2 f = __half22float2(__ldg(Z2 + s * 32 + lane));
                    acc.x += f.x; acc.y += f.y;
                }
            }
            acc.x = fmaxf(acc.x, 0.f);
            acc.y = fmaxf(acc.y, 0.f);
            sh[rloc][2 * lane]     = acc.x;
            sh[rloc][2 * lane + 1] = acc.y;
        }
    } else {
        for (int i = t; i < 1024; i += 256) {
            int r = i >> 4, kc = (i & 15) * 4;
            int gr = row0 + r;
            float4 v = make_float4(0.f, 0.f, 0.f, 0.f);
            if (gr < N_NODES) v = *reinterpret_cast<const float4*>(H + (size_t)gr * 64 + kc);
            *reinterpret_cast<float4*>(&sh[r][kc]) = v;
        }
    }
    __syncthreads();

    const int tx = t & 15, ty = t >> 4;
    unsigned long long a0[4][2] = {};
    unsigned long long a1[4][2] = {};

    #pragma unroll 4
    for (int k4 = 0; k4 < 16; k4++) {
        float4 hq0 = *reinterpret_cast<const float4*>(&sh[ty     ][k4 * 4]);
        float4 hq1 = *reinterpret_cast<const float4*>(&sh[ty + 16][k4 * 4]);
        float4 hq2 = *reinterpret_cast<const float4*>(&sh[ty + 32][k4 * 4]);
        float4 hq3 = *reinterpret_cast<const float4*>(&sh[ty + 48][k4 * 4]);
        float ha0[4] = {hq0.x, hq0.y, hq0.z, hq0.w};
        float ha1[4] = {hq1.x, hq1.y, hq1.z, hq1.w};
        float ha2[4] = {hq2.x, hq2.y, hq2.z, hq2.w};
        float ha3[4] = {hq3.x, hq3.y, hq3.z, hq3.w};
        #pragma unroll
        for (int kk = 0; kk < 4; kk++) {
            int k = k4 * 4 + kk;
            float4 w0q = *reinterpret_cast<const float4*>(&sw0[k][tx * 4]);
            float4 w1q = *reinterpret_cast<const float4*>(&sw1[k][tx * 4]);
            unsigned long long w0p0 = pack2(w0q.x, w0q.y), w0p1 = pack2(w0q.z, w0q.w);
            unsigned long long w1p0 = pack2(w1q.x, w1q.y), w1p1 = pack2(w1q.z, w1q.w);
            unsigned long long hp;
            hp = pack2(ha0[kk], ha0[kk]);
            ffma2(a0[0][0], hp, w0p0); ffma2(a0[0][1], hp, w0p1);
            ffma2(a1[0][0], hp, w1p0); ffma2(a1[0][1], hp, w1p1);
            hp = pack2(ha1[kk], ha1[kk]);
            ffma2(a0[1][0], hp, w0p0); ffma2(a0[1][1], hp, w0p1);
            ffma2(a1[1][0], hp, w1p0); ffma2(a1[1][1], hp, w1p1);
            hp = pack2(ha2[kk], ha2[kk]);
            ffma2(a0[2][0], hp, w0p0); ffma2(a0[2][1], hp, w0p1);
            ffma2(a1[2][0], hp, w1p0); ffma2(a1[2][1], hp, w1p1);
            hp = pack2(ha3[kk], ha3[kk]);
            ffma2(a0[3][0], hp, w0p0); ffma2(a0[3][1], hp, w0p1);
            ffma2(a1[3][0], hp, w1p0); ffma2(a1[3][1], hp, w1p1);
        }
    }

    const float scale = g_scale;
    const int cbase = tx * 4;
    float4 bq = make_float4(0.f, 0.f, 0.f, 0.f);
    if (cbase < COUT) bq = *reinterpret_cast<const float4*>(B + cbase);

    #pragma unroll
    for (int r = 0; r < 4; r++) {
        int gr = row0 + ty + 16 * r;
        if (gr >= N_NODES || cbase >= COUT) continue;
        float nl = (float)g_deg_src[gr] * scale - 1.0f;
        float p0, p1, p2, p3, z0, z1, z2, z3;
        unpack2(a0[r][0], p0, p1); unpack2(a0[r][1], p2, p3);
        unpack2(a1[r][0], z0, z1); unpack2(a1[r][1], z2, z3);
        float4 outq;
        outq.x = p0 + bq.x + nl * z0;
        outq.y = p1 + bq.y + nl * z1;
        outq.z = p2 + bq.z + nl * z2;
        outq.w = p3 + bq.w + nl * z3;
        *reinterpret_cast<float4*>(P0 + (size_t)gr * 64 + cbase) = outq;
        __half2 h0 = __floats2half2_rn(-scale * z0, -scale * z1);
        __half2 h1 = __floats2half2_rn(-scale * z2, -scale * z3);
        uint2 hz = make_uint2(*reinterpret_cast<unsigned*>(&h0),
                              *reinterpret_cast<unsigned*>(&h1));
        *reinterpret_cast<uint2*>(Zh + (size_t)gr * 64 + cbase) = hz;
    }
}

// ---------------- final: gather (40 ch) fused with log_softmax ----------------
__global__ __launch_bounds__(256)
void cheb_gather40_lsm(const float* __restrict__ P0,
                       const __half* __restrict__ Zh,
                       float* __restrict__ out)
{
    int warp = (blockIdx.x * blockDim.x + threadIdx.x) >> 5;
    int lane = threadIdx.x & 31;
    if (warp >= N_NODES) return;
    const __half2* Z2 = reinterpret_cast<const __half2*>(Zh);
    int beg = g_row_start[warp], end = g_row_start[warp + 1];
    float2 acc = make_float2(0.f, 0.f);
    bool act = lane < 20;
    int e = beg;
    for (; e + 4 <= end; e += 4) {
        int s0 = __ldg(&g_csr_src[e + 0]);
        int s1 = __ldg(&g_csr_src[e + 1]);
        int s2 = __ldg(&g_csr_src[e + 2]);
        int s3 = __ldg(&g_csr_src[e + 3]);
        if (act) {
            float2 f0 = __half22float2(__ldg(Z2 + s0 * 32 + lane));
            float2 f1 = __half22float2(__ldg(Z2 + s1 * 32 + lane));
            float2 f2 = __half22float2(__ldg(Z2 + s2 * 32 + lane));
            float2 f3 = __half22float2(__ldg(Z2 + s3 * 32 + lane));
            acc.x += (f0.x + f1.x) + (f2.x + f3.x);
            acc.y += (f0.y + f1.y) + (f2.y + f3.y);
        }
    }
    for (; e < end; e++) {
        int s = __ldg(&g_csr_src[e]);
        if (act) {
            float2 f = __half22float2(__ldg(Z2 + s * 32 + lane));
            acc.x += f.x; acc.y += f.y;
        }
    }
    float v0 = -3.0e38f, v1 = -3.0e38f;
    if (act) {
        float2 p = *reinterpret_cast<const float2*>(P0 + (size_t)warp * 64 + 2 * lane);
        v0 = p.x + acc.x;
        v1 = p.y + acc.y;
    }
    float m = fmaxf(v0, v1);
    #pragma unroll
    for (int o = 16; o; o >>= 1) m = fmaxf(m, __shfl_xor_sync(0xFFFFFFFFu, m, o));
    float s = act ? (expf(v0 - m) + expf(v1 - m)) : 0.f;
    #pragma unroll
    for (int o = 16; o; o >>= 1) s += __shfl_xor_sync(0xFFFFFFFFu, s, o);
    float ls = m + logf(s);
    if (act) {
        float2 o2 = make_float2(v0 - ls, v1 - ls);
        *reinterpret_cast<float2*>(out + (size_t)warp * 40 + 2 * lane) = o2;
    }
}

// ---------------- launch ------------------------------------------------------
extern "C" void kernel_launch(void* const* d_in, const int* in_sizes, int n_in,
                              void* d_out, int out_size)
{
    const float* x    = (const float*)d_in[0];
    const int*   ei   = (const int*)d_in[1];
    const int*   esrc = ei;
    const int*   edst = ei + E_EDGES;
    const float* W0_0 = (const float*)d_in[2];
    const float* W1_0 = (const float*)d_in[3];
    const float* b_0  = (const float*)d_in[4];
    const float* W0_1 = (const float*)d_in[5];
    const float* W1_1 = (const float*)d_in[6];
    const float* b_1  = (const float*)d_in[7];
    const float* W0_2 = (const float*)d_in[8];
    const float* W1_2 = (const float*)d_in[9];
    const float* b_2  = (const float*)d_in[10];

    float *bufP0, *bufP1;
    __half *bufZ0, *bufZ1;
    cudaGetSymbolAddress((void**)&bufP0, g_bufP0);
    cudaGetSymbolAddress((void**)&bufP1, g_bufP1);
    cudaGetSymbolAddress((void**)&bufZ0, g_bufZ0);
    cudaGetSymbolAddress((void**)&bufZ1, g_bufZ1);

    const int NB_N = (N_NODES + 255) / 256;
    const int NB_E = (E_EDGES + 255) / 256;
    const int NB_G = (N_NODES + 63) / 64;
    const int NB_W = (N_NODES * 32 + 255) / 256;

    // norm + CSR build (6 launches)
    k_init<<<NB_N, 256>>>();
    k_deg<<<NB_E, 256>>>(esrc, edst);
    k_scan1<<<NB_SCAN, 256>>>();
    k_scan2<<<1, 1>>>();
    k_scan3<<<NB_N, 256>>>();
    k_fill<<<NB_E, 256>>>(esrc, edst);

    // Layer 0: raw x -> P0_0, Z0
    cheb_gemm<64, false><<<NB_G, 256>>>(x, nullptr, nullptr,
                                        W0_0, W1_0, b_0, bufP0, bufZ0);
    // Layer 1: gather(P0_0, Z0) + relu -> P0_1, Z1
    cheb_gemm<64, true><<<NB_G, 256>>>(nullptr, bufP0, bufZ0,
                                       W0_1, W1_1, b_1, bufP1, bufZ1);
    // Layer 2: gather(P0_1, Z1) + relu -> P0_0, Z0 (40 ch)
    cheb_gemm<40, true><<<NB_G, 256>>>(nullptr, bufP1, bufZ1,
                                       W0_2, W1_2, b_2, bufP0, bufZ0);
    // Final gather40 + log_softmax
    cheb_gather40_lsm<<<NB_W, 256>>>(bufP0, bufZ0, (float*)d_out);
}

// round 7
// speedup vs baseline: 1.1330x; 1.1330x over previous
#include <cuda_runtime.h>
#include <cuda_fp16.h>
#include <cstdint>

#define N_NODES 100000
#define E_EDGES 1600000
#define SCAN_CHUNK 1024
#define NB_SCAN ((N_NODES + SCAN_CHUNK - 1) / SCAN_CHUNK)   // 98
#define NB_E 6250          // edge blocks (256 threads each)
#define NB_G 1563          // gemm blocks (64 rows each)
#define NB_COMBO (NB_G * 5) // 7815: every 5th block is a gemm block

// ---------------- scratch (device globals; no allocation allowed) -------------
__device__ int    g_deg_src[N_NODES];
__device__ int    g_deg_dst[N_NODES];
__device__ int    g_cursor[N_NODES];
__device__ int    g_row_start[N_NODES + 1];
__device__ int    g_blockSums[NB_SCAN];
__device__ int    g_csr_src[E_EDGES];
__device__ int    g_maxdeg;
__device__ float  g_scale;
__device__ float  g_bufP0[(size_t)N_NODES * 64];
__device__ float  g_bufP1[(size_t)N_NODES * 64];
__device__ __half g_bufZ0[(size_t)N_NODES * 64];

// ---------------- packed fp32x2 helpers ---------------------------------------
__device__ __forceinline__ unsigned long long pack2(float a, float b) {
    unsigned long long r;
    asm("mov.b64 %0, {%1, %2};" : "=l"(r) : "f"(a), "f"(b));
    return r;
}
__device__ __forceinline__ void unpack2(unsigned long long p, float& a, float& b) {
    asm("mov.b64 {%0, %1}, %2;" : "=f"(a), "=f"(b) : "l"(p));
}
__device__ __forceinline__ void ffma2(unsigned long long& d,
                                      unsigned long long a, unsigned long long b) {
    asm("fma.rn.f32x2 %0, %1, %2, %0;" : "+l"(d) : "l"(a), "l"(b));
}

// ---------------- dual GEMM body (FFMA2), raw outputs -------------------------
// P0[i,c] = (h@W0)[i,c] + b[c]        (fp32)
// Zh[i,c] = fp16( (h@W1)[i,c] )       (raw z; norm applied in gather)
template<int COUT, bool RELU>
__device__ __forceinline__
void gemm_body(int gblk,
               const float* __restrict__ H,
               const float* __restrict__ W0,
               const float* __restrict__ W1,
               const float* __restrict__ B,
               float* __restrict__ P0,
               __half* __restrict__ Zh)
{
    __shared__ float sh[64][68];
    __shared__ float sw0[64][64];
    __shared__ float sw1[64][64];

    const int t    = threadIdx.x;
    const int row0 = gblk * 64;

    for (int i = t; i < 64 * 64; i += 256) {
        int k = i >> 6, c = i & 63;
        float a = 0.f, bb = 0.f;
        if (c < COUT) { a = W0[k * COUT + c]; bb = W1[k * COUT + c]; }
        sw0[k][c] = a;
        sw1[k][c] = bb;
    }
    for (int i = t; i < 1024; i += 256) {
        int r = i >> 4, kc = (i & 15) * 4;
        int gr = row0 + r;
        float4 v = make_float4(0.f, 0.f, 0.f, 0.f);
        if (gr < N_NODES) v = *reinterpret_cast<const float4*>(H + (size_t)gr * 64 + kc);
        if (RELU) {
            v.x = fmaxf(v.x, 0.f); v.y = fmaxf(v.y, 0.f);
            v.z = fmaxf(v.z, 0.f); v.w = fmaxf(v.w, 0.f);
        }
        *reinterpret_cast<float4*>(&sh[r][kc]) = v;
    }
    __syncthreads();

    const int tx = t & 15, ty = t >> 4;
    unsigned long long a0[4][2] = {};
    unsigned long long a1[4][2] = {};

    #pragma unroll 4
    for (int k4 = 0; k4 < 16; k4++) {
        float4 hq0 = *reinterpret_cast<const float4*>(&sh[ty     ][k4 * 4]);
        float4 hq1 = *reinterpret_cast<const float4*>(&sh[ty + 16][k4 * 4]);
        float4 hq2 = *reinterpret_cast<const float4*>(&sh[ty + 32][k4 * 4]);
        float4 hq3 = *reinterpret_cast<const float4*>(&sh[ty + 48][k4 * 4]);
        float ha0[4] = {hq0.x, hq0.y, hq0.z, hq0.w};
        float ha1[4] = {hq1.x, hq1.y, hq1.z, hq1.w};
        float ha2[4] = {hq2.x, hq2.y, hq2.z, hq2.w};
        float ha3[4] = {hq3.x, hq3.y, hq3.z, hq3.w};
        #pragma unroll
        for (int kk = 0; kk < 4; kk++) {
            int k = k4 * 4 + kk;
            float4 w0q = *reinterpret_cast<const float4*>(&sw0[k][tx * 4]);
            float4 w1q = *reinterpret_cast<const float4*>(&sw1[k][tx * 4]);
            unsigned long long w0p0 = pack2(w0q.x, w0q.y), w0p1 = pack2(w0q.z, w0q.w);
            unsigned long long w1p0 = pack2(w1q.x, w1q.y), w1p1 = pack2(w1q.z, w1q.w);
            unsigned long long hp;
            hp = pack2(ha0[kk], ha0[kk]);
            ffma2(a0[0][0], hp, w0p0); ffma2(a0[0][1], hp, w0p1);
            ffma2(a1[0][0], hp, w1p0); ffma2(a1[0][1], hp, w1p1);
            hp = pack2(ha1[kk], ha1[kk]);
            ffma2(a0[1][0], hp, w0p0); ffma2(a0[1][1], hp, w0p1);
            ffma2(a1[1][0], hp, w1p0); ffma2(a1[1][1], hp, w1p1);
            hp = pack2(ha2[kk], ha2[kk]);
            ffma2(a0[2][0], hp, w0p0); ffma2(a0[2][1], hp, w0p1);
            ffma2(a1[2][0], hp, w1p0); ffma2(a1[2][1], hp, w1p1);
            hp = pack2(ha3[kk], ha3[kk]);
            ffma2(a0[3][0], hp, w0p0); ffma2(a0[3][1], hp, w0p1);
            ffma2(a1[3][0], hp, w1p0); ffma2(a1[3][1], hp, w1p1);
        }
    }

    const int cbase = tx * 4;
    float4 bq = make_float4(0.f, 0.f, 0.f, 0.f);
    if (cbase < COUT) bq = *reinterpret_cast<const float4*>(B + cbase);

    #pragma unroll
    for (int r = 0; r < 4; r++) {
        int gr = row0 + ty + 16 * r;
        if (gr >= N_NODES || cbase >= COUT) continue;
        float p0, p1, p2, p3, z0, z1, z2, z3;
        unpack2(a0[r][0], p0, p1); unpack2(a0[r][1], p2, p3);
        unpack2(a1[r][0], z0, z1); unpack2(a1[r][1], z2, z3);
        float4 outq = make_float4(p0 + bq.x, p1 + bq.y, p2 + bq.z, p3 + bq.w);
        *reinterpret_cast<float4*>(P0 + (size_t)gr * 64 + cbase) = outq;
        __half2 h0 = __floats2half2_rn(z0, z1);
        __half2 h1 = __floats2half2_rn(z2, z3);
        uint2 hz = make_uint2(*reinterpret_cast<unsigned*>(&h0),
                              *reinterpret_cast<unsigned*>(&h1));
        *reinterpret_cast<uint2*>(Zh + (size_t)gr * 64 + cbase) = hz;
    }
}

// ---------------- prologue kernels --------------------------------------------
__global__ void k_init()
{
    int i = blockIdx.x * blockDim.x + threadIdx.x;
    if (i < N_NODES) { g_deg_src[i] = 0; g_deg_dst[i] = 0; }
    if (i == 0) g_maxdeg = 0;
}

// combined: degree counting blocks interleaved 4:1 with layer-0 GEMM blocks
__global__ __launch_bounds__(256, 3)
void k_combo(const int* __restrict__ esrc, const int* __restrict__ edst,
             const float* __restrict__ X,
             const float* __restrict__ W0, const float* __restrict__ W1,
             const float* __restrict__ B,
             float* __restrict__ P0, __half* __restrict__ Zh)
{
    int bid = blockIdx.x;
    int q = bid / 5, r = bid - q * 5;
    if (r == 4) {
        gemm_body<64, false>(q, X, W0, W1, B, P0, Zh);
    } else {
        int degIdx = bid - q;
        int e = degIdx * 256 + threadIdx.x;
        if (e < E_EDGES) {
            atomicAdd(&g_deg_src[esrc[e]], 1);
            atomicAdd(&g_deg_dst[edst[e]], 1);
        }
    }
}

// exclusive scan of deg_dst (chunk pass) + max-reduce of deg_src
__global__ __launch_bounds__(256) void k_scan1()
{
    __shared__ int warp_tot[8];
    __shared__ int warp_max[8];
    int b = blockIdx.x, t = threadIdx.x;
    int base = b * SCAN_CHUNK + t * 4;
    int v0 = (base + 0 < N_NODES) ? g_deg_dst[base + 0] : 0;
    int v1 = (base + 1 < N_NODES) ? g_deg_dst[base + 1] : 0;
    int v2 = (base + 2 < N_NODES) ? g_deg_dst[base + 2] : 0;
    int v3 = (base + 3 < N_NODES) ? g_deg_dst[base + 3] : 0;
    int m0 = (base + 0 < N_NODES) ? g_deg_src[base + 0] : 0;
    int m1 = (base + 1 < N_NODES) ? g_deg_src[base + 1] : 0;
    int m2 = (base + 2 < N_NODES) ? g_deg_src[base + 2] : 0;
    int m3 = (base + 3 < N_NODES) ? g_deg_src[base + 3] : 0;
    int s1 = v0, s2 = s1 + v1, s3 = s2 + v2, tot = s3 + v3;
    int mx = max(max(m0, m1), max(m2, m3));

    int lane = t & 31, w = t >> 5;
    int inc = tot;
    #pragma unroll
    for (int o = 1; o < 32; o <<= 1) {
        int n = __shfl_up_sync(0xFFFFFFFFu, inc, o);
        if (lane >= o) inc += n;
    }
    #pragma unroll
    for (int o = 16; o; o >>= 1) mx = max(mx, __shfl_xor_sync(0xFFFFFFFFu, mx, o));
    if (lane == 31) warp_tot[w] = inc;
    if (lane == 0)  warp_max[w] = mx;
    __syncthreads();
    if (t == 0) {
        int run = 0, bm = 0;
        #pragma unroll
        for (int i = 0; i < 8; i++) {
            int x = warp_tot[i]; warp_tot[i] = run; run += x;
            bm = max(bm, warp_max[i]);
        }
        g_blockSums[b] = run;
        atomicMax(&g_maxdeg, bm);
    }
    __syncthreads();
    int excl = warp_tot[w] + (inc - tot);
    if (base + 0 < N_NODES) g_row_start[base + 0] = excl;
    if (base + 1 < N_NODES) g_row_start[base + 1] = excl + s1;
    if (base + 2 < N_NODES) g_row_start[base + 2] = excl + s2;
    if (base + 3 < N_NODES) g_row_start[base + 3] = excl + s3;
}

// finalize row_start (adds per-chunk offsets scanned locally) + cursor + scale
__global__ __launch_bounds__(256) void k_scan3()
{
    __shared__ int soff[NB_SCAN];
    int t = threadIdx.x;
    if (t < NB_SCAN) soff[t] = g_blockSums[t];
    __syncthreads();
    if (t == 0) {
        int run = 0;
        #pragma unroll 1
        for (int b = 0; b < NB_SCAN; b++) { int x = soff[b]; soff[b] = run; run += x; }
    }
    __syncthreads();
    int i = blockIdx.x * 256 + t;
    if (i < N_NODES) {
        int rs = g_row_start[i] + soff[i >> 10];
        g_row_start[i] = rs;
        g_cursor[i] = rs;
    }
    if (i == 0) {
        g_row_start[N_NODES] = E_EDGES;
        g_scale = 1.0f / (float)max(g_maxdeg, 1);
    }
}

__global__ void k_fill(const int* __restrict__ esrc, const int* __restrict__ edst)
{
    int e = blockIdx.x * blockDim.x + threadIdx.x;
    if (e < E_EDGES) {
        int d = edst[e];
        int pos = atomicAdd(&g_cursor[d], 1);
        g_csr_src[pos] = esrc[e];
    }
}

// ---------------- standalone GEMM kernels (layers 1, 2) -----------------------
template<int COUT, bool RELU>
__global__ __launch_bounds__(256, 3)
void cheb_gemm(const float* __restrict__ H,
               const float* __restrict__ W0,
               const float* __restrict__ W1,
               const float* __restrict__ B,
               float* __restrict__ P0,
               __half* __restrict__ Zh)
{
    gemm_body<COUT, RELU>(blockIdx.x, H, W0, W1, B, P0, Zh);
}

// ---------------- CSR gather, 2 edges per warp-iteration ----------------------
// Out[i] = P0[i] + (deg_src[i]*scale - 1)*z[i] - scale * sum_{e in in(i)} z[src_e]
__global__ __launch_bounds__(256)
void cheb_gather64(const float* __restrict__ P0,
                   const __half* __restrict__ Zh,
                   float* __restrict__ Out)
{
    int warp = (blockIdx.x * blockDim.x + threadIdx.x) >> 5;
    int lane = threadIdx.x & 31;
    if (warp >= N_NODES) return;
    const int half = lane >> 4;        // which edge of the pair
    const int c4   = lane & 15;        // channel quad (4 ch)
    const uint2* Zv = reinterpret_cast<const uint2*>(Zh);  // 16 uint2 per row

    int beg = g_row_start[warp], end = g_row_start[warp + 1];
    float4 acc = make_float4(0.f, 0.f, 0.f, 0.f);
    int e = beg;
    #pragma unroll 1
    for (; e + 8 <= end; e += 8) {
        #pragma unroll
        for (int u = 0; u < 4; u++) {
            int s = __ldg(&g_csr_src[e + 2 * u + half]);
            uint2 d = __ldg(Zv + (size_t)s * 16 + c4);
            __half2 h0 = *reinterpret_cast<__half2*>(&d.x);
            __half2 h1 = *reinterpret_cast<__half2*>(&d.y);
            float2 f0 = __half22float2(h0), f1 = __half22float2(h1);
            acc.x += f0.x; acc.y += f0.y; acc.z += f1.x; acc.w += f1.y;
        }
    }
    for (; e < end; e += 2) {
        int ee = e + half;
        if (ee < end) {
            int s = __ldg(&g_csr_src[ee]);
            uint2 d = __ldg(Zv + (size_t)s * 16 + c4);
            __half2 h0 = *reinterpret_cast<__half2*>(&d.x);
            __half2 h1 = *reinterpret_cast<__half2*>(&d.y);
            float2 f0 = __half22float2(h0), f1 = __half22float2(h1);
            acc.x += f0.x; acc.y += f0.y; acc.z += f1.x; acc.w += f1.y;
        }
    }
    acc.x += __shfl_xor_sync(0xFFFFFFFFu, acc.x, 16);
    acc.y += __shfl_xor_sync(0xFFFFFFFFu, acc.y, 16);
    acc.z += __shfl_xor_sync(0xFFFFFFFFu, acc.z, 16);
    acc.w += __shfl_xor_sync(0xFFFFFFFFu, acc.w, 16);

    if (half == 0) {
        float scale = g_scale;
        float nl = (float)__ldg(&g_deg_src[warp]) * scale - 1.0f;
        uint2 dz = __ldg(Zv + (size_t)warp * 16 + c4);
        __half2 z0h = *reinterpret_cast<__half2*>(&dz.x);
        __half2 z1h = *reinterpret_cast<__half2*>(&dz.y);
        float2 z0 = __half22float2(z0h), z1 = __half22float2(z1h);
        float4 p = __ldg(reinterpret_cast<const float4*>(P0 + (size_t)warp * 64) + c4);
        float4 o;
        o.x = p.x + nl * z0.x - scale * acc.x;
        o.y = p.y + nl * z0.y - scale * acc.y;
        o.z = p.z + nl * z1.x - scale * acc.z;
        o.w = p.w + nl * z1.y - scale * acc.w;
        reinterpret_cast<float4*>(Out + (size_t)warp * 64)[c4] = o;
    }
}

// ---------------- final: gather (40 ch) fused with log_softmax ----------------
__global__ __launch_bounds__(256)
void cheb_gather40_lsm(const float* __restrict__ P0,
                       const __half* __restrict__ Zh,
                       float* __restrict__ out)
{
    int warp = (blockIdx.x * blockDim.x + threadIdx.x) >> 5;
    int lane = threadIdx.x & 31;
    if (warp >= N_NODES) return;
    const __half2* Z2 = reinterpret_cast<const __half2*>(Zh);
    int beg = g_row_start[warp], end = g_row_start[warp + 1];
    float2 acc = make_float2(0.f, 0.f);
    bool act = lane < 20;
    int e = beg;
    for (; e + 4 <= end; e += 4) {
        int s0 = __ldg(&g_csr_src[e + 0]);
        int s1 = __ldg(&g_csr_src[e + 1]);
        int s2 = __ldg(&g_csr_src[e + 2]);
        int s3 = __ldg(&g_csr_src[e + 3]);
        if (act) {
            float2 f0 = __half22float2(__ldg(Z2 + (size_t)s0 * 32 + lane));
            float2 f1 = __half22float2(__ldg(Z2 + (size_t)s1 * 32 + lane));
            float2 f2 = __half22float2(__ldg(Z2 + (size_t)s2 * 32 + lane));
            float2 f3 = __half22float2(__ldg(Z2 + (size_t)s3 * 32 + lane));
            acc.x += (f0.x + f1.x) + (f2.x + f3.x);
            acc.y += (f0.y + f1.y) + (f2.y + f3.y);
        }
    }
    for (; e < end; e++) {
        int s = __ldg(&g_csr_src[e]);
        if (act) {
            float2 f = __half22float2(__ldg(Z2 + (size_t)s * 32 + lane));
            acc.x += f.x; acc.y += f.y;
        }
    }
    float v0 = -3.0e38f, v1 = -3.0e38f;
    if (act) {
        float scale = g_scale;
        float nl = (float)__ldg(&g_deg_src[warp]) * scale - 1.0f;
        float2 zs = __half22float2(__ldg(Z2 + (size_t)warp * 32 + lane));
        float2 p = *reinterpret_cast<const float2*>(P0 + (size_t)warp * 64 + 2 * lane);
        v0 = p.x + nl * zs.x - scale * acc.x;
        v1 = p.y + nl * zs.y - scale * acc.y;
    }
    float m = fmaxf(v0, v1);
    #pragma unroll
    for (int o = 16; o; o >>= 1) m = fmaxf(m, __shfl_xor_sync(0xFFFFFFFFu, m, o));
    float s = act ? (expf(v0 - m) + expf(v1 - m)) : 0.f;
    #pragma unroll
    for (int o = 16; o; o >>= 1) s += __shfl_xor_sync(0xFFFFFFFFu, s, o);
    float ls = m + logf(s);
    if (act) {
        float2 o2 = make_float2(v0 - ls, v1 - ls);
        *reinterpret_cast<float2*>(out + (size_t)warp * 40 + 2 * lane) = o2;
    }
}

// ---------------- launch ------------------------------------------------------
extern "C" void kernel_launch(void* const* d_in, const int* in_sizes, int n_in,
                              void* d_out, int out_size)
{
    const float* x    = (const float*)d_in[0];
    const int*   ei   = (const int*)d_in[1];
    const int*   esrc = ei;
    const int*   edst = ei + E_EDGES;
    const float* W0_0 = (const float*)d_in[2];
    const float* W1_0 = (const float*)d_in[3];
    const float* b_0  = (const float*)d_in[4];
    const float* W0_1 = (const float*)d_in[5];
    const float* W1_1 = (const float*)d_in[6];
    const float* b_1  = (const float*)d_in[7];
    const float* W0_2 = (const float*)d_in[8];
    const float* W1_2 = (const float*)d_in[9];
    const float* b_2  = (const float*)d_in[10];

    float *bufP0, *bufP1;
    __half *bufZ0;
    cudaGetSymbolAddress((void**)&bufP0, g_bufP0);
    cudaGetSymbolAddress((void**)&bufP1, g_bufP1);
    cudaGetSymbolAddress((void**)&bufZ0, g_bufZ0);

    const int NB_N = (N_NODES + 255) / 256;          // 391
    const int NB_W = (N_NODES * 32 + 255) / 256;     // 12500

    // prologue: init, then degree-count interleaved with layer-0 GEMM
    k_init<<<NB_N, 256>>>();
    k_combo<<<NB_COMBO, 256>>>(esrc, edst, x, W0_0, W1_0, b_0, bufP0, bufZ0);
    k_scan1<<<NB_SCAN, 256>>>();
    k_scan3<<<NB_N, 256>>>();
    k_fill<<<NB_E, 256>>>(esrc, edst);

    // Layer 0 aggregate -> H1 (pre-relu)
    cheb_gather64<<<NB_W, 256>>>(bufP0, bufZ0, bufP1);
    // Layer 1
    cheb_gemm<64, true><<<NB_G, 256>>>(bufP1, W0_1, W1_1, b_1, bufP0, bufZ0);
    cheb_gather64<<<NB_W, 256>>>(bufP0, bufZ0, bufP1);
    // Layer 2
    cheb_gemm<40, true><<<NB_G, 256>>>(bufP1, W0_2, W1_2, b_2, bufP0, bufZ0);
    // Final aggregate + log_softmax
    cheb_gather40_lsm<<<NB_W, 256>>>(bufP0, bufZ0, (float*)d_out);
}

// round 9
// speedup vs baseline: 1.1371x; 1.0036x over previous
#include <cuda_runtime.h>
#include <cuda_fp16.h>
#include <cstdint>

#define N_NODES 100000
#define E_EDGES 1600000
#define SCAN_CHUNK 1024
#define NB_SCAN ((N_NODES + SCAN_CHUNK - 1) / SCAN_CHUNK)   // 98
#define NB_E 6250           // edge blocks (256 threads each)
#define NB_G 1563           // gemm blocks (64 rows each)
#define NB_COMBO (NB_G * 5) // every 5th block is a gemm block

// ---------------- scratch (device globals; no allocation allowed) -------------
// Zero-invariant: g_deg_src, g_deg_dst, g_maxdeg are zero at entry of every
// kernel_launch call (zero-init at load; each call re-zeros them after last
// use, so graph replays preserve the invariant).
__device__ int    g_deg_src[N_NODES];
__device__ int    g_deg_dst[N_NODES];
__device__ int    g_cursor[N_NODES];
__device__ int    g_row_start[N_NODES + 1];
__device__ int    g_blockSums[NB_SCAN];
__device__ int    g_csr_src[E_EDGES];
__device__ int    g_maxdeg;
__device__ float  g_scale;
__device__ float  g_bufP0[(size_t)N_NODES * 64];
__device__ float  g_bufP1[(size_t)N_NODES * 64];
__device__ __half g_bufZ0[(size_t)N_NODES * 64];

// ---------------- packed fp32x2 helpers ---------------------------------------
__device__ __forceinline__ unsigned long long pack2(float a, float b) {
    unsigned long long r;
    asm("mov.b64 %0, {%1, %2};" : "=l"(r) : "f"(a), "f"(b));
    return r;
}
__device__ __forceinline__ void unpack2(unsigned long long p, float& a, float& b) {
    asm("mov.b64 {%0, %1}, %2;" : "=f"(a), "=f"(b) : "l"(p));
}
__device__ __forceinline__ void ffma2(unsigned long long& d,
                                      unsigned long long a, unsigned long long b) {
    asm("fma.rn.f32x2 %0, %1, %2, %0;" : "+l"(d) : "l"(a), "l"(b));
}

// ---------------- dual GEMM body (FFMA2), raw outputs -------------------------
// P0[i,c] = (h@W0)[i,c] + b[c]        (fp32)
// Zh[i,c] = fp16( (h@W1)[i,c] )       (raw z; norm applied in gather)
template<int COUT, bool RELU>
__device__ __forceinline__
void gemm_body(int gblk,
               const float* __restrict__ H,
               const float* __restrict__ W0,
               const float* __restrict__ W1,
               const float* __restrict__ B,
               float* __restrict__ P0,
               __half* __restrict__ Zh)
{
    __shared__ float sh[64][68];
    __shared__ float sw0[64][64];
    __shared__ float sw1[64][64];

    const int t    = threadIdx.x;
    const int row0 = gblk * 64;

    for (int i = t; i < 64 * 64; i += 256) {
        int k = i >> 6, c = i & 63;
        float a = 0.f, bb = 0.f;
        if (c < COUT) { a = W0[k * COUT + c]; bb = W1[k * COUT + c]; }
        sw0[k][c] = a;
        sw1[k][c] = bb;
    }
    for (int i = t; i < 1024; i += 256) {
        int r = i >> 4, kc = (i & 15) * 4;
        int gr = row0 + r;
        float4 v = make_float4(0.f, 0.f, 0.f, 0.f);
        if (gr < N_NODES) v = *reinterpret_cast<const float4*>(H + (size_t)gr * 64 + kc);
        if (RELU) {
            v.x = fmaxf(v.x, 0.f); v.y = fmaxf(v.y, 0.f);
            v.z = fmaxf(v.z, 0.f); v.w = fmaxf(v.w, 0.f);
        }
        *reinterpret_cast<float4*>(&sh[r][kc]) = v;
    }
    __syncthreads();

    const int tx = t & 15, ty = t >> 4;
    unsigned long long a0[4][2] = {};
    unsigned long long a1[4][2] = {};

    #pragma unroll 4
    for (int k4 = 0; k4 < 16; k4++) {
        float4 hq0 = *reinterpret_cast<const float4*>(&sh[ty     ][k4 * 4]);
        float4 hq1 = *reinterpret_cast<const float4*>(&sh[ty + 16][k4 * 4]);
        float4 hq2 = *reinterpret_cast<const float4*>(&sh[ty + 32][k4 * 4]);
        float4 hq3 = *reinterpret_cast<const float4*>(&sh[ty + 48][k4 * 4]);
        float ha0[4] = {hq0.x, hq0.y, hq0.z, hq0.w};
        float ha1[4] = {hq1.x, hq1.y, hq1.z, hq1.w};
        float ha2[4] = {hq2.x, hq2.y, hq2.z, hq2.w};
        float ha3[4] = {hq3.x, hq3.y, hq3.z, hq3.w};
        #pragma unroll
        for (int kk = 0; kk < 4; kk++) {
            int k = k4 * 4 + kk;
            float4 w0q = *reinterpret_cast<const float4*>(&sw0[k][tx * 4]);
            float4 w1q = *reinterpret_cast<const float4*>(&sw1[k][tx * 4]);
            unsigned long long w0p0 = pack2(w0q.x, w0q.y), w0p1 = pack2(w0q.z, w0q.w);
            unsigned long long w1p0 = pack2(w1q.x, w1q.y), w1p1 = pack2(w1q.z, w1q.w);
            unsigned long long hp;
            hp = pack2(ha0[kk], ha0[kk]);
            ffma2(a0[0][0], hp, w0p0); ffma2(a0[0][1], hp, w0p1);
            ffma2(a1[0][0], hp, w1p0); ffma2(a1[0][1], hp, w1p1);
            hp = pack2(ha1[kk], ha1[kk]);
            ffma2(a0[1][0], hp, w0p0); ffma2(a0[1][1], hp, w0p1);
            ffma2(a1[1][0], hp, w1p0); ffma2(a1[1][1], hp, w1p1);
            hp = pack2(ha2[kk], ha2[kk]);
            ffma2(a0[2][0], hp, w0p0); ffma2(a0[2][1], hp, w0p1);
            ffma2(a1[2][0], hp, w1p0); ffma2(a1[2][1], hp, w1p1);
            hp = pack2(ha3[kk], ha3[kk]);
            ffma2(a0[3][0], hp, w0p0); ffma2(a0[3][1], hp, w0p1);
            ffma2(a1[3][0], hp, w1p0); ffma2(a1[3][1], hp, w1p1);
        }
    }

    const int cbase = tx * 4;
    float4 bq = make_float4(0.f, 0.f, 0.f, 0.f);
    if (cbase < COUT) bq = *reinterpret_cast<const float4*>(B + cbase);

    #pragma unroll
    for (int r = 0; r < 4; r++) {
        int gr = row0 + ty + 16 * r;
        if (gr >= N_NODES || cbase >= COUT) continue;
        float p0, p1, p2, p3, z0, z1, z2, z3;
        unpack2(a0[r][0], p0, p1); unpack2(a0[r][1], p2, p3);
        unpack2(a1[r][0], z0, z1); unpack2(a1[r][1], z2, z3);
        float4 outq = make_float4(p0 + bq.x, p1 + bq.y, p2 + bq.z, p3 + bq.w);
        *reinterpret_cast<float4*>(P0 + (size_t)gr * 64 + cbase) = outq;
        __half2 h0 = __floats2half2_rn(z0, z1);
        __half2 h1 = __floats2half2_rn(z2, z3);
        uint2 hz = make_uint2(*reinterpret_cast<unsigned*>(&h0),
                              *reinterpret_cast<unsigned*>(&h1));
        *reinterpret_cast<uint2*>(Zh + (size_t)gr * 64 + cbase) = hz;
    }
}

// ---------------- prologue kernels --------------------------------------------
// degree counting interleaved 4:1 with layer-0 GEMM
__global__ __launch_bounds__(256, 3)
void k_combo(const int* __restrict__ esrc, const int* __restrict__ edst,
             const float* __restrict__ X,
             const float* __restrict__ W0, const float* __restrict__ W1,
             const float* __restrict__ B,
             float* __restrict__ P0, __half* __restrict__ Zh)
{
    int bid = blockIdx.x;
    int q = bid / 5, r = bid - q * 5;
    if (r == 4) {
        gemm_body<64, false>(q, X, W0, W1, B, P0, Zh);
    } else {
        int degIdx = bid - q;
        int e = degIdx * 256 + threadIdx.x;
        if (e < E_EDGES) {
            atomicAdd(&g_deg_src[esrc[e]], 1);
            atomicAdd(&g_deg_dst[edst[e]], 1);
        }
    }
}

// exclusive scan of deg_dst (chunk-local pass) + max-reduce of deg_src
__global__ __launch_bounds__(256) void k_scan1()
{
    __shared__ int warp_tot[8];
    __shared__ int warp_max[8];
    int b = blockIdx.x, t = threadIdx.x;
    int base = b * SCAN_CHUNK + t * 4;
    int v0 = (base + 0 < N_NODES) ? g_deg_dst[base + 0] : 0;
    int v1 = (base + 1 < N_NODES) ? g_deg_dst[base + 1] : 0;
    int v2 = (base + 2 < N_NODES) ? g_deg_dst[base + 2] : 0;
    int v3 = (base + 3 < N_NODES) ? g_deg_dst[base + 3] : 0;
    int m0 = (base + 0 < N_NODES) ? g_deg_src[base + 0] : 0;
    int m1 = (base + 1 < N_NODES) ? g_deg_src[base + 1] : 0;
    int m2 = (base + 2 < N_NODES) ? g_deg_src[base + 2] : 0;
    int m3 = (base + 3 < N_NODES) ? g_deg_src[base + 3] : 0;
    int s1 = v0, s2 = s1 + v1, s3 = s2 + v2, tot = s3 + v3;
    int mx = max(max(m0, m1), max(m2, m3));

    int lane = t & 31, w = t >> 5;
    int inc = tot;
    #pragma unroll
    for (int o = 1; o < 32; o <<= 1) {
        int n = __shfl_up_sync(0xFFFFFFFFu, inc, o);
        if (lane >= o) inc += n;
    }
    #pragma unroll
    for (int o = 16; o; o >>= 1) mx = max(mx, __shfl_xor_sync(0xFFFFFFFFu, mx, o));
    if (lane == 31) warp_tot[w] = inc;
    if (lane == 0)  warp_max[w] = mx;
    __syncthreads();
    if (t == 0) {
        int run = 0, bm = 0;
        #pragma unroll
        for (int i = 0; i < 8; i++) {
            int x = warp_tot[i]; warp_tot[i] = run; run += x;
            bm = max(bm, warp_max[i]);
        }
        g_blockSums[b] = run;
        atomicMax(&g_maxdeg, bm);
    }
    __syncthreads();
    int excl = warp_tot[w] + (inc - tot);
    if (base + 0 < N_NODES) g_row_start[base + 0] = excl;
    if (base + 1 < N_NODES) g_row_start[base + 1] = excl + s1;
    if (base + 2 < N_NODES) g_row_start[base + 2] = excl + s2;
    if (base + 3 < N_NODES) g_row_start[base + 3] = excl + s3;
}

// finalize row_start: parallel scan of the 98 chunk sums (redundant per block)
__global__ __launch_bounds__(256) void k_scan3()
{
    __shared__ int soff[128];
    int t = threadIdx.x;
    if (t < 128) soff[t] = (t < NB_SCAN) ? g_blockSums[t] : 0;
    __syncthreads();
    #pragma unroll
    for (int o = 1; o < 128; o <<= 1) {
        int v = 0;
        if (t < 128 && t >= o) v = soff[t - o];
        __syncthreads();
        if (t < 128) soff[t] += v;
        __syncthreads();
    }
    int i = blockIdx.x * 256 + t;
    if (i < N_NODES) {
        int c = i >> 10;
        int off = (c == 0) ? 0 : soff[c - 1];
        int rs = g_row_start[i] + off;
        g_row_start[i] = rs;
        g_cursor[i] = rs;
    }
    if (i == 0) {
        g_row_start[N_NODES] = E_EDGES;
        g_scale = 1.0f / (float)max(g_maxdeg, 1);
    }
}

// CSR fill; also restores zero-invariant for deg_dst and maxdeg (read is done)
__global__ void k_fill(const int* __restrict__ esrc, const int* __restrict__ edst)
{
    int e = blockIdx.x * blockDim.x + threadIdx.x;
    if (e < N_NODES) g_deg_dst[e] = 0;
    if (e == 0) g_maxdeg = 0;
    if (e < E_EDGES) {
        int d = edst[e];
        int pos = atomicAdd(&g_cursor[d], 1);
        g_csr_src[pos] = esrc[e];
    }
}

// ---------------- standalone GEMM kernels (layers 1, 2) -----------------------
template<int COUT, bool RELU>
__global__ __launch_bounds__(256, 3)
void cheb_gemm(const float* __restrict__ H,
               const float* __restrict__ W0,
               const float* __restrict__ W1,
               const float* __restrict__ B,
               float* __restrict__ P0,
               __half* __restrict__ Zh)
{
    gemm_body<COUT, RELU>(blockIdx.x, H, W0, W1, B, P0, Zh);
}

// ---------------- CSR gather, 2 edges per warp-iteration ----------------------
// Out[i] = P0[i] + (deg_src[i]*scale - 1)*z[i] - scale * sum_{e in in(i)} z[src_e]
__global__ __launch_bounds__(256)
void cheb_gather64(const float* __restrict__ P0,
                   const __half* __restrict__ Zh,
                   float* __restrict__ Out)
{
    int warp = (blockIdx.x * blockDim.x + threadIdx.x) >> 5;
    int lane = threadIdx.x & 31;
    if (warp >= N_NODES) return;
    const int half = lane >> 4;        // which edge of the pair
    const int c4   = lane & 15;        // channel quad (4 ch)
    const uint2* Zv = reinterpret_cast<const uint2*>(Zh);  // 16 uint2 per row

    int beg = g_row_start[warp], end = g_row_start[warp + 1];
    float4 acc = make_float4(0.f, 0.f, 0.f, 0.f);
    int e = beg;
    #pragma unroll 1
    for (; e + 8 <= end; e += 8) {
        #pragma unroll
        for (int u = 0; u < 4; u++) {
            int s = __ldg(&g_csr_src[e + 2 * u + half]);
            uint2 d = __ldg(Zv + (size_t)s * 16 + c4);
            __half2 h0 = *reinterpret_cast<__half2*>(&d.x);
            __half2 h1 = *reinterpret_cast<__half2*>(&d.y);
            float2 f0 = __half22float2(h0), f1 = __half22float2(h1);
            acc.x += f0.x; acc.y += f0.y; acc.z += f1.x; acc.w += f1.y;
        }
    }
    for (; e < end; e += 2) {
        int ee = e + half;
        if (ee < end) {
            int s = __ldg(&g_csr_src[ee]);
            uint2 d = __ldg(Zv + (size_t)s * 16 + c4);
            __half2 h0 = *reinterpret_cast<__half2*>(&d.x);
            __half2 h1 = *reinterpret_cast<__half2*>(&d.y);
            float2 f0 = __half22float2(h0), f1 = __half22float2(h1);
            acc.x += f0.x; acc.y += f0.y; acc.z += f1.x; acc.w += f1.y;
        }
    }
    acc.x += __shfl_xor_sync(0xFFFFFFFFu, acc.x, 16);
    acc.y += __shfl_xor_sync(0xFFFFFFFFu, acc.y, 16);
    acc.z += __shfl_xor_sync(0xFFFFFFFFu, acc.z, 16);
    acc.w += __shfl_xor_sync(0xFFFFFFFFu, acc.w, 16);

    if (half == 0) {
        float scale = g_scale;
        float nl = (float)__ldg(&g_deg_src[warp]) * scale - 1.0f;
        uint2 dz = __ldg(Zv + (size_t)warp * 16 + c4);
        __half2 z0h = *reinterpret_cast<__half2*>(&dz.x);
        __half2 z1h = *reinterpret_cast<__half2*>(&dz.y);
        float2 z0 = __half22float2(z0h), z1 = __half22float2(z1h);
        float4 p = __ldg(reinterpret_cast<const float4*>(P0 + (size_t)warp * 64) + c4);
        float4 o;
        o.x = p.x + nl * z0.x - scale * acc.x;
        o.y = p.y + nl * z0.y - scale * acc.y;
        o.z = p.z + nl * z1.x - scale * acc.z;
        o.w = p.w + nl * z1.y - scale * acc.w;
        reinterpret_cast<float4*>(Out + (size_t)warp * 64)[c4] = o;
    }
}

// ---------------- final: gather (40 ch) + log_softmax; resets deg_src ---------
__global__ __launch_bounds__(256)
void cheb_gather40_lsm(const float* __restrict__ P0,
                       const __half* __restrict__ Zh,
                       float* __restrict__ out)
{
    int warp = (blockIdx.x * blockDim.x + threadIdx.x) >> 5;
    int lane = threadIdx.x & 31;
    if (warp >= N_NODES) return;
    const __half2* Z2 = reinterpret_cast<const __half2*>(Zh);
    int beg = g_row_start[warp], end = g_row_start[warp + 1];
    float2 acc = make_float2(0.f, 0.f);
    bool act = lane < 20;
    int e = beg;
    for (; e + 4 <= end; e += 4) {
        int s0 = __ldg(&g_csr_src[e + 0]);
        int s1 = __ldg(&g_csr_src[e + 1]);
        int s2 = __ldg(&g_csr_src[e + 2]);
        int s3 = __ldg(&g_csr_src[e + 3]);
        if (act) {
            float2 f0 = __half22float2(__ldg(Z2 + (size_t)s0 * 32 + lane));
            float2 f1 = __half22float2(__ldg(Z2 + (size_t)s1 * 32 + lane));
            float2 f2 = __half22float2(__ldg(Z2 + (size_t)s2 * 32 + lane));
            float2 f3 = __half22float2(__ldg(Z2 + (size_t)s3 * 32 + lane));
            acc.x += (f0.x + f1.x) + (f2.x + f3.x);
            acc.y += (f0.y + f1.y) + (f2.y + f3.y);
        }
    }
    for (; e < end; e++) {
        int s = __ldg(&g_csr_src[e]);
        if (act) {
            float2 f = __half22float2(__ldg(Z2 + (size_t)s * 32 + lane));
            acc.x += f.x; acc.y += f.y;
        }
    }
    float v0 = -3.0e38f, v1 = -3.0e38f;
    if (act) {
        float scale = g_scale;
        float nl = (float)__ldg(&g_deg_src[warp]) * scale - 1.0f;
        float2 zs = __half22float2(__ldg(Z2 + (size_t)warp * 32 + lane));
        float2 p = *reinterpret_cast<const float2*>(P0 + (size_t)warp * 64 + 2 * lane);
        v0 = p.x + nl * zs.x - scale * acc.x;
        v1 = p.y + nl * zs.y - scale * acc.y;
    }
    float m = fmaxf(v0, v1);
    #pragma unroll
    for (int o = 16; o; o >>= 1) m = fmaxf(m, __shfl_xor_sync(0xFFFFFFFFu, m, o));
    float s = act ? (expf(v0 - m) + expf(v1 - m)) : 0.f;
    #pragma unroll
    for (int o = 16; o; o >>= 1) s += __shfl_xor_sync(0xFFFFFFFFu, s, o);
    float ls = m + logf(s);
    if (act) {
        float2 o2 = make_float2(v0 - ls, v1 - ls);
        *reinterpret_cast<float2*>(out + (size_t)warp * 40 + 2 * lane) = o2;
    }
    // restore zero-invariant for next call (all reads of deg_src are done)
    __syncwarp();
    if (lane == 0) g_deg_src[warp] = 0;
}

// ---------------- launch ------------------------------------------------------
extern "C" void kernel_launch(void* const* d_in, const int* in_sizes, int n_in,
                              void* d_out, int out_size)
{
    const float* x    = (const float*)d_in[0];
    const int*   ei   = (const int*)d_in[1];
    const int*   esrc = ei;
    const int*   edst = ei + E_EDGES;
    const float* W0_0 = (const float*)d_in[2];
    const float* W1_0 = (const float*)d_in[3];
    const float* b_0  = (const float*)d_in[4];
    const float* W0_1 = (const float*)d_in[5];
    const float* W1_1 = (const float*)d_in[6];
    const float* b_1  = (const float*)d_in[7];
    const float* W0_2 = (const float*)d_in[8];
    const float* W1_2 = (const float*)d_in[9];
    const float* b_2  = (const float*)d_in[10];

    float *bufP0, *bufP1;
    __half *bufZ0;
    cudaGetSymbolAddress((void**)&bufP0, g_bufP0);
    cudaGetSymbolAddress((void**)&bufP1, g_bufP1);
    cudaGetSymbolAddress((void**)&bufZ0, g_bufZ0);

    const int NB_N = (N_NODES + 255) / 256;          // 391
    const int NB_W = (N_NODES * 32 + 255) / 256;     // 12500

    // prologue: degree-count interleaved with layer-0 GEMM, then scan + fill
    k_combo<<<NB_COMBO, 256>>>(esrc, edst, x, W0_0, W1_0, b_0, bufP0, bufZ0);
    k_scan1<<<NB_SCAN, 256>>>();
    k_scan3<<<NB_N, 256>>>();
    k_fill<<<NB_E, 256>>>(esrc, edst);

    // Layer 0 aggregate -> H1 (pre-relu)
    cheb_gather64<<<NB_W, 256>>>(bufP0, bufZ0, bufP1);
    // Layer 1
    cheb_gemm<64, true><<<NB_G, 256>>>(bufP1, W0_1, W1_1, b_1, bufP0, bufZ0);
    cheb_gather64<<<NB_W, 256>>>(bufP0, bufZ0, bufP1);
    // Layer 2
    cheb_gemm<40, true><<<NB_G, 256>>>(bufP1, W0_2, W1_2, b_2, bufP0, bufZ0);
    // Final aggregate + log_softmax (also resets deg_src invariant)
    cheb_gather40_lsm<<<NB_W, 256>>>(bufP0, bufZ0, (float*)d_out);
}

// round 10
// speedup vs baseline: 1.4771x; 1.2990x over previous
#include <cuda_runtime.h>
#include <cuda_fp16.h>
#include <cstdint>

#define N_NODES 100000
#define E_EDGES 1600000
#define SCAN_CHUNK 1024
#define NB_SCAN ((N_NODES + SCAN_CHUNK - 1) / SCAN_CHUNK)   // 98
#define NB_E 6250           // edge blocks (256 threads each)
#define NB_G 1563           // gemm blocks (64 rows each)
#define NB_COMBO (NB_G * 5) // every 5th block is a gemm block

// ---------------- scratch (device globals; no allocation allowed) -------------
// Zero-invariant: g_deg_src, g_deg_dst, g_maxdeg are zero at entry of every
// kernel_launch call (zero-init at load; each call re-zeros them after last
// use, so graph replays preserve the invariant).
__device__ int    g_deg_src[N_NODES];
__device__ int    g_deg_dst[N_NODES];
__device__ int    g_cursor[N_NODES];
__device__ int    g_row_start[N_NODES + 1];
__device__ int    g_blockSums[NB_SCAN];
__device__ int    g_csr_src[E_EDGES];
__device__ int    g_maxdeg;
__device__ float  g_scale;
__device__ float  g_bufP0[(size_t)N_NODES * 64];
__device__ float  g_bufP1[(size_t)N_NODES * 64];
__device__ __half g_bufZ0[(size_t)N_NODES * 64];

// ---------------- mma / ldmatrix helpers --------------------------------------
__device__ __forceinline__ uint32_t smem_u32(const void* p) {
    return (uint32_t)__cvta_generic_to_shared(p);
}
__device__ __forceinline__ void ldsm_x4(uint32_t* r, uint32_t addr) {
    asm volatile("ldmatrix.sync.aligned.m8n8.x4.shared.b16 {%0,%1,%2,%3}, [%4];"
                 : "=r"(r[0]), "=r"(r[1]), "=r"(r[2]), "=r"(r[3]) : "r"(addr));
}
__device__ __forceinline__ void ldsm_x4t(uint32_t* r, uint32_t addr) {
    asm volatile("ldmatrix.sync.aligned.m8n8.x4.trans.shared.b16 {%0,%1,%2,%3}, [%4];"
                 : "=r"(r[0]), "=r"(r[1]), "=r"(r[2]), "=r"(r[3]) : "r"(addr));
}
__device__ __forceinline__ void mma16816(float* c, const uint32_t* a,
                                         uint32_t b0, uint32_t b1) {
    asm volatile("mma.sync.aligned.m16n8k16.row.col.f32.f16.f16.f32 "
                 "{%0,%1,%2,%3}, {%4,%5,%6,%7}, {%8,%9}, {%0,%1,%2,%3};"
                 : "+f"(c[0]), "+f"(c[1]), "+f"(c[2]), "+f"(c[3])
                 : "r"(a[0]), "r"(a[1]), "r"(a[2]), "r"(a[3]), "r"(b0), "r"(b1));
}

// ---------------- tensor-core dual GEMM body ----------------------------------
// Warps 0-3: P0[i,c] = (h@W0)[i,c] + b[c]  (fp32)
// Warps 4-7: Zh[i,c] = fp16((h@W1)[i,c])
// fp32 H input, converted (with optional ReLU) to fp16 in smem.
// COUT: logical out cols; NTP: n-tile pairs (covers 16*NTP cols).
template<int COUT, int NTP, bool RELU>
__device__ __forceinline__
void gemm_body16(int gblk,
                 const float* __restrict__ H,
                 const float* __restrict__ W0,
                 const float* __restrict__ W1,
                 const float* __restrict__ B,
                 float* __restrict__ P0,
                 __half* __restrict__ Zh)
{
    // NOTE: alignas(16) is load-bearing — ldmatrix requires 16B-aligned
    // addresses; bare __half arrays are only 2B-aligned (R8 NaN root cause).
    __shared__ alignas(16) __half sH[64][72];
    __shared__ alignas(16) __half sW[2][64][72];
    const int t    = threadIdx.x;
    const int row0 = gblk * 64;

    // weights -> fp16 smem (zero-pad cols >= COUT up to 64)
    for (int i = t; i < 4096; i += 256) {
        int k = i >> 6, c = i & 63;
        float w0 = 0.f, w1 = 0.f;
        if (c < COUT) { w0 = W0[k * COUT + c]; w1 = W1[k * COUT + c]; }
        sW[0][k][c] = __float2half(w0);
        sW[1][k][c] = __float2half(w1);
    }
    // H tile (fp32 -> optional relu -> fp16)
    for (int i = t; i < 1024; i += 256) {
        int r = i >> 4, c = (i & 15) * 4;
        int gr = row0 + r;
        float4 v = make_float4(0.f, 0.f, 0.f, 0.f);
        if (gr < N_NODES) v = *reinterpret_cast<const float4*>(H + (size_t)gr * 64 + c);
        if (RELU) {
            v.x = fmaxf(v.x, 0.f); v.y = fmaxf(v.y, 0.f);
            v.z = fmaxf(v.z, 0.f); v.w = fmaxf(v.w, 0.f);
        }
        *reinterpret_cast<__half2*>(&sH[r][c])     = __floats2half2_rn(v.x, v.y);
        *reinterpret_cast<__half2*>(&sH[r][c + 2]) = __floats2half2_rn(v.z, v.w);
    }
    __syncthreads();

    const int lane = t & 31, wid = t >> 5;
    const int mat = wid >> 2;              // 0 -> W0/P0, 1 -> W1/Zh
    const int mrow = (wid & 3) * 16;       // 16 M-rows per warp
    float acc[2 * NTP][4];
    #pragma unroll
    for (int i = 0; i < 2 * NTP; i++) { acc[i][0] = acc[i][1] = acc[i][2] = acc[i][3] = 0.f; }

    const int arow  = mrow + (lane & 15);
    const int ahalf = (lane >> 4) * 8;
    const int krow  = (lane & 7) + ((lane >> 3) & 1) * 8;
    const int ncOff = (lane >> 4) * 8;

    #pragma unroll
    for (int kk = 0; kk < 4; kk++) {
        uint32_t a[4];
        ldsm_x4(a, smem_u32(&sH[arow][kk * 16 + ahalf]));
        #pragma unroll
        for (int p = 0; p < NTP; p++) {
            uint32_t b4[4];
            ldsm_x4t(b4, smem_u32(&sW[mat][kk * 16 + krow][p * 16 + ncOff]));
            mma16816(acc[2 * p],     a, b4[0], b4[1]);
            mma16816(acc[2 * p + 1], a, b4[2], b4[3]);
        }
    }

    // C frag: rows (g, g+8) = lane>>2, cols 2*(lane&3) within each n8 tile
    const int g   = lane >> 2;
    const int cp  = (lane & 3) * 2;
    const int gr0 = row0 + mrow + g;
    const int gr1 = gr0 + 8;
    if (mat == 0) {
        #pragma unroll
        for (int nt = 0; nt < 2 * NTP; nt++) {
            int gc = nt * 8 + cp;
            if (gc >= COUT) continue;
            float b0 = __ldg(B + gc), b1 = __ldg(B + gc + 1);
            if (gr0 < N_NODES)
                *reinterpret_cast<float2*>(P0 + (size_t)gr0 * 64 + gc) =
                    make_float2(acc[nt][0] + b0, acc[nt][1] + b1);
            if (gr1 < N_NODES)
                *reinterpret_cast<float2*>(P0 + (size_t)gr1 * 64 + gc) =
                    make_float2(acc[nt][2] + b0, acc[nt][3] + b1);
        }
    } else {
        #pragma unroll
        for (int nt = 0; nt < 2 * NTP; nt++) {
            int gc = nt * 8 + cp;
            if (gc >= COUT) continue;
            if (gr0 < N_NODES) {
                __half2 h = __floats2half2_rn(acc[nt][0], acc[nt][1]);
                *reinterpret_cast<__half2*>(Zh + (size_t)gr0 * 64 + gc) = h;
            }
            if (gr1 < N_NODES) {
                __half2 h = __floats2half2_rn(acc[nt][2], acc[nt][3]);
                *reinterpret_cast<__half2*>(Zh + (size_t)gr1 * 64 + gc) = h;
            }
        }
    }
}

// ---------------- prologue kernels --------------------------------------------
// degree counting interleaved 4:1 with layer-0 GEMM
__global__ __launch_bounds__(256)
void k_combo(const int* __restrict__ esrc, const int* __restrict__ edst,
             const float* __restrict__ X,
             const float* __restrict__ W0, const float* __restrict__ W1,
             const float* __restrict__ B,
             float* __restrict__ P0, __half* __restrict__ Zh)
{
    int bid = blockIdx.x;
    int q = bid / 5, r = bid - q * 5;
    if (r == 4) {
        gemm_body16<64, 4, false>(q, X, W0, W1, B, P0, Zh);
    } else {
        int degIdx = bid - q;
        int e = degIdx * 256 + threadIdx.x;
        if (e < E_EDGES) {
            atomicAdd(&g_deg_src[esrc[e]], 1);
            atomicAdd(&g_deg_dst[edst[e]], 1);
        }
    }
}

// exclusive scan of deg_dst (chunk-local pass) + max-reduce of deg_src
__global__ __launch_bounds__(256) void k_scan1()
{
    __shared__ int warp_tot[8];
    __shared__ int warp_max[8];
    int b = blockIdx.x, t = threadIdx.x;
    int base = b * SCAN_CHUNK + t * 4;
    int v0 = (base + 0 < N_NODES) ? g_deg_dst[base + 0] : 0;
    int v1 = (base + 1 < N_NODES) ? g_deg_dst[base + 1] : 0;
    int v2 = (base + 2 < N_NODES) ? g_deg_dst[base + 2] : 0;
    int v3 = (base + 3 < N_NODES) ? g_deg_dst[base + 3] : 0;
    int m0 = (base + 0 < N_NODES) ? g_deg_src[base + 0] : 0;
    int m1 = (base + 1 < N_NODES) ? g_deg_src[base + 1] : 0;
    int m2 = (base + 2 < N_NODES) ? g_deg_src[base + 2] : 0;
    int m3 = (base + 3 < N_NODES) ? g_deg_src[base + 3] : 0;
    int s1 = v0, s2 = s1 + v1, s3 = s2 + v2, tot = s3 + v3;
    int mx = max(max(m0, m1), max(m2, m3));

    int lane = t & 31, w = t >> 5;
    int inc = tot;
    #pragma unroll
    for (int o = 1; o < 32; o <<= 1) {
        int n = __shfl_up_sync(0xFFFFFFFFu, inc, o);
        if (lane >= o) inc += n;
    }
    #pragma unroll
    for (int o = 16; o; o >>= 1) mx = max(mx, __shfl_xor_sync(0xFFFFFFFFu, mx, o));
    if (lane == 31) warp_tot[w] = inc;
    if (lane == 0)  warp_max[w] = mx;
    __syncthreads();
    if (t == 0) {
        int run = 0, bm = 0;
        #pragma unroll
        for (int i = 0; i < 8; i++) {
            int x = warp_tot[i]; warp_tot[i] = run; run += x;
            bm = max(bm, warp_max[i]);
        }
        g_blockSums[b] = run;
        atomicMax(&g_maxdeg, bm);
    }
    __syncthreads();
    int excl = warp_tot[w] + (inc - tot);
    if (base + 0 < N_NODES) g_row_start[base + 0] = excl;
    if (base + 1 < N_NODES) g_row_start[base + 1] = excl + s1;
    if (base + 2 < N_NODES) g_row_start[base + 2] = excl + s2;
    if (base + 3 < N_NODES) g_row_start[base + 3] = excl + s3;
}

// finalize row_start: parallel scan of the 98 chunk sums (redundant per block)
__global__ __launch_bounds__(256) void k_scan3()
{
    __shared__ int soff[128];
    int t = threadIdx.x;
    if (t < 128) soff[t] = (t < NB_SCAN) ? g_blockSums[t] : 0;
    __syncthreads();
    #pragma unroll
    for (int o = 1; o < 128; o <<= 1) {
        int v = 0;
        if (t < 128 && t >= o) v = soff[t - o];
        __syncthreads();
        if (t < 128) soff[t] += v;
        __syncthreads();
    }
    int i = blockIdx.x * 256 + t;
    if (i < N_NODES) {
        int c = i >> 10;
        int off = (c == 0) ? 0 : soff[c - 1];
        int rs = g_row_start[i] + off;
        g_row_start[i] = rs;
        g_cursor[i] = rs;
    }
    if (i == 0) {
        g_row_start[N_NODES] = E_EDGES;
        g_scale = 1.0f / (float)max(g_maxdeg, 1);
    }
}

// CSR fill; also restores zero-invariant for deg_dst and maxdeg (read is done)
__global__ void k_fill(const int* __restrict__ esrc, const int* __restrict__ edst)
{
    int e = blockIdx.x * blockDim.x + threadIdx.x;
    if (e < N_NODES) g_deg_dst[e] = 0;
    if (e == 0) g_maxdeg = 0;
    if (e < E_EDGES) {
        int d = edst[e];
        int pos = atomicAdd(&g_cursor[d], 1);
        g_csr_src[pos] = esrc[e];
    }
}

// ---------------- standalone tensor-core GEMM kernels (layers 1, 2) -----------
template<int COUT, int NTP, bool RELU>
__global__ __launch_bounds__(256)
void cheb_gemm16(const float* __restrict__ H,
                 const float* __restrict__ W0, const float* __restrict__ W1,
                 const float* __restrict__ B,
                 float* __restrict__ P0, __half* __restrict__ Zh)
{
    gemm_body16<COUT, NTP, RELU>(blockIdx.x, H, W0, W1, B, P0, Zh);
}

// ---------------- CSR gather, 2 edges per warp-iteration ----------------------
// Out[i] = P0[i] + (deg_src[i]*scale - 1)*z[i] - scale * sum_{e in in(i)} z[src_e]
__global__ __launch_bounds__(256)
void cheb_gather64(const float* __restrict__ P0,
                   const __half* __restrict__ Zh,
                   float* __restrict__ Out)
{
    int warp = (blockIdx.x * blockDim.x + threadIdx.x) >> 5;
    int lane = threadIdx.x & 31;
    if (warp >= N_NODES) return;
    const int half = lane >> 4;        // which edge of the pair
    const int c4   = lane & 15;        // channel quad (4 ch)
    const uint2* Zv = reinterpret_cast<const uint2*>(Zh);  // 16 uint2 per row

    int beg = g_row_start[warp], end = g_row_start[warp + 1];
    float4 acc = make_float4(0.f, 0.f, 0.f, 0.f);
    int e = beg;
    #pragma unroll 1
    for (; e + 8 <= end; e += 8) {
        #pragma unroll
        for (int u = 0; u < 4; u++) {
            int s = __ldg(&g_csr_src[e + 2 * u + half]);
            uint2 d = __ldg(Zv + (size_t)s * 16 + c4);
            __half2 h0 = *reinterpret_cast<__half2*>(&d.x);
            __half2 h1 = *reinterpret_cast<__half2*>(&d.y);
            float2 f0 = __half22float2(h0), f1 = __half22float2(h1);
            acc.x += f0.x; acc.y += f0.y; acc.z += f1.x; acc.w += f1.y;
        }
    }
    for (; e < end; e += 2) {
        int ee = e + half;
        if (ee < end) {
            int s = __ldg(&g_csr_src[ee]);
            uint2 d = __ldg(Zv + (size_t)s * 16 + c4);
            __half2 h0 = *reinterpret_cast<__half2*>(&d.x);
            __half2 h1 = *reinterpret_cast<__half2*>(&d.y);
            float2 f0 = __half22float2(h0), f1 = __half22float2(h1);
            acc.x += f0.x; acc.y += f0.y; acc.z += f1.x; acc.w += f1.y;
        }
    }
    acc.x += __shfl_xor_sync(0xFFFFFFFFu, acc.x, 16);
    acc.y += __shfl_xor_sync(0xFFFFFFFFu, acc.y, 16);
    acc.z += __shfl_xor_sync(0xFFFFFFFFu, acc.z, 16);
    acc.w += __shfl_xor_sync(0xFFFFFFFFu, acc.w, 16);

    if (half == 0) {
        float scale = g_scale;
        float nl = (float)__ldg(&g_deg_src[warp]) * scale - 1.0f;
        uint2 dz = __ldg(Zv + (size_t)warp * 16 + c4);
        __half2 z0h = *reinterpret_cast<__half2*>(&dz.x);
        __half2 z1h = *reinterpret_cast<__half2*>(&dz.y);
        float2 z0 = __half22float2(z0h), z1 = __half22float2(z1h);
        float4 p = __ldg(reinterpret_cast<const float4*>(P0 + (size_t)warp * 64) + c4);
        float4 o;
        o.x = p.x + nl * z0.x - scale * acc.x;
        o.y = p.y + nl * z0.y - scale * acc.y;
        o.z = p.z + nl * z1.x - scale * acc.z;
        o.w = p.w + nl * z1.y - scale * acc.w;
        reinterpret_cast<float4*>(Out + (size_t)warp * 64)[c4] = o;
    }
}

// ---------------- final: gather (40 ch) + log_softmax; resets deg_src ---------
__global__ __launch_bounds__(256)
void cheb_gather40_lsm(const float* __restrict__ P0,
                       const __half* __restrict__ Zh,
                       float* __restrict__ out)
{
    int warp = (blockIdx.x * blockDim.x + threadIdx.x) >> 5;
    int lane = threadIdx.x & 31;
    if (warp >= N_NODES) return;
    const __half2* Z2 = reinterpret_cast<const __half2*>(Zh);
    int beg = g_row_start[warp], end = g_row_start[warp + 1];
    float2 acc = make_float2(0.f, 0.f);
    bool act = lane < 20;
    int e = beg;
    for (; e + 4 <= end; e += 4) {
        int s0 = __ldg(&g_csr_src[e + 0]);
        int s1 = __ldg(&g_csr_src[e + 1]);
        int s2 = __ldg(&g_csr_src[e + 2]);
        int s3 = __ldg(&g_csr_src[e + 3]);
        if (act) {
            float2 f0 = __half22float2(__ldg(Z2 + (size_t)s0 * 32 + lane));
            float2 f1 = __half22float2(__ldg(Z2 + (size_t)s1 * 32 + lane));
            float2 f2 = __half22float2(__ldg(Z2 + (size_t)s2 * 32 + lane));
            float2 f3 = __half22float2(__ldg(Z2 + (size_t)s3 * 32 + lane));
            acc.x += (f0.x + f1.x) + (f2.x + f3.x);
            acc.y += (f0.y + f1.y) + (f2.y + f3.y);
        }
    }
    for (; e < end; e++) {
        int s = __ldg(&g_csr_src[e]);
        if (act) {
            float2 f = __half22float2(__ldg(Z2 + (size_t)s * 32 + lane));
            acc.x += f.x; acc.y += f.y;
        }
    }
    float v0 = -3.0e38f, v1 = -3.0e38f;
    if (act) {
        float scale = g_scale;
        float nl = (float)__ldg(&g_deg_src[warp]) * scale - 1.0f;
        float2 zs = __half22float2(__ldg(Z2 + (size_t)warp * 32 + lane));
        float2 p = *reinterpret_cast<const float2*>(P0 + (size_t)warp * 64 + 2 * lane);
        v0 = p.x + nl * zs.x - scale * acc.x;
        v1 = p.y + nl * zs.y - scale * acc.y;
    }
    float m = fmaxf(v0, v1);
    #pragma unroll
    for (int o = 16; o; o >>= 1) m = fmaxf(m, __shfl_xor_sync(0xFFFFFFFFu, m, o));
    float s = act ? (expf(v0 - m) + expf(v1 - m)) : 0.f;
    #pragma unroll
    for (int o = 16; o; o >>= 1) s += __shfl_xor_sync(0xFFFFFFFFu, s, o);
    float ls = m + logf(s);
    if (act) {
        float2 o2 = make_float2(v0 - ls, v1 - ls);
        *reinterpret_cast<float2*>(out + (size_t)warp * 40 + 2 * lane) = o2;
    }
    // restore zero-invariant for next call (all reads of deg_src are done)
    __syncwarp();
    if (lane == 0) g_deg_src[warp] = 0;
}

// ---------------- launch ------------------------------------------------------
extern "C" void kernel_launch(void* const* d_in, const int* in_sizes, int n_in,
                              void* d_out, int out_size)
{
    const float* x    = (const float*)d_in[0];
    const int*   ei   = (const int*)d_in[1];
    const int*   esrc = ei;
    const int*   edst = ei + E_EDGES;
    const float* W0_0 = (const float*)d_in[2];
    const float* W1_0 = (const float*)d_in[3];
    const float* b_0  = (const float*)d_in[4];
    const float* W0_1 = (const float*)d_in[5];
    const float* W1_1 = (const float*)d_in[6];
    const float* b_1  = (const float*)d_in[7];
    const float* W0_2 = (const float*)d_in[8];
    const float* W1_2 = (const float*)d_in[9];
    const float* b_2  = (const float*)d_in[10];

    float *bufP0, *bufP1;
    __half *bufZ0;
    cudaGetSymbolAddress((void**)&bufP0, g_bufP0);
    cudaGetSymbolAddress((void**)&bufP1, g_bufP1);
    cudaGetSymbolAddress((void**)&bufZ0, g_bufZ0);

    const int NB_N = (N_NODES + 255) / 256;          // 391
    const int NB_W = (N_NODES * 32 + 255) / 256;     // 12500

    // prologue: degree-count interleaved with layer-0 GEMM, then scan + fill
    k_combo<<<NB_COMBO, 256>>>(esrc, edst, x, W0_0, W1_0, b_0, bufP0, bufZ0);
    k_scan1<<<NB_SCAN, 256>>>();
    k_scan3<<<NB_N, 256>>>();
    k_fill<<<NB_E, 256>>>(esrc, edst);

    // Layer 0 aggregate -> H1 (pre-relu)
    cheb_gather64<<<NB_W, 256>>>(bufP0, bufZ0, bufP1);
    // Layer 1 (tensor cores; relu on load)
    cheb_gemm16<64, 4, true><<<NB_G, 256>>>(bufP1, W0_1, W1_1, b_1, bufP0, bufZ0);
    cheb_gather64<<<NB_W, 256>>>(bufP0, bufZ0, bufP1);
    // Layer 2 (tensor cores, 40 cols -> 3 n-tile pairs; relu on load)
    cheb_gemm16<40, 3, true><<<NB_G, 256>>>(bufP1, W0_2, W1_2, b_2, bufP0, bufZ0);
    // Final aggregate + log_softmax (also resets deg_src invariant)
    cheb_gather40_lsm<<<NB_W, 256>>>(bufP0, bufZ0, (float*)d_out);
}

// round 12
// speedup vs baseline: 1.8066x; 1.2230x over previous
#include <cuda_runtime.h>
#include <cuda_fp16.h>
#include <cstdint>

#define N_NODES 100000
#define E_EDGES 1600000
#define SCAN_CHUNK 1024
#define NB_SCAN ((N_NODES + SCAN_CHUNK - 1) / SCAN_CHUNK)   // 98
#define NB_E 6250           // edge blocks (256 threads each)
#define NB_G 1563           // gemm blocks (64 rows each)
#define NB_COMBO (NB_G * 5) // every 5th block is a gemm block; +2 wconv blocks

// ---------------- scratch (device globals; no allocation allowed) -------------
// Zero-invariant: g_deg_src, g_deg_dst, g_maxdeg are zero at entry of every
// kernel_launch call (zero-init at load; each call re-zeros them after last
// use, so graph replays preserve the invariant).
__device__ int    g_deg_src[N_NODES];
__device__ int    g_deg_dst[N_NODES];
__device__ int    g_cursor[N_NODES];
__device__ int    g_row_start[N_NODES + 1];
__device__ int    g_blockSums[NB_SCAN];
__device__ int    g_csr_src[E_EDGES];
__device__ int    g_maxdeg;
__device__ float  g_scale;
__device__ float  g_bufP0[(size_t)N_NODES * 64];   // fp32 h@W0 + b
__device__ __half g_bufZ0[(size_t)N_NODES * 64];   // fp16 h@W1 (raw z)
__device__ __half g_bufH[(size_t)N_NODES * 64];    // fp16 activations (pre-relu)
__device__ __half g_w1h[2 * 64 * 64];              // layer-1 W0|W1 fp16
__device__ __half g_w2h[2 * 64 * 64];              // layer-2 W0|W1 fp16 (zero-padded)

// ---------------- mma / ldmatrix helpers --------------------------------------
__device__ __forceinline__ uint32_t smem_u32(const void* p) {
    return (uint32_t)__cvta_generic_to_shared(p);
}
__device__ __forceinline__ void ldsm_x4(uint32_t* r, uint32_t addr) {
    asm volatile("ldmatrix.sync.aligned.m8n8.x4.shared.b16 {%0,%1,%2,%3}, [%4];"
                 : "=r"(r[0]), "=r"(r[1]), "=r"(r[2]), "=r"(r[3]) : "r"(addr));
}
__device__ __forceinline__ void ldsm_x4t(uint32_t* r, uint32_t addr) {
    asm volatile("ldmatrix.sync.aligned.m8n8.x4.trans.shared.b16 {%0,%1,%2,%3}, [%4];"
                 : "=r"(r[0]), "=r"(r[1]), "=r"(r[2]), "=r"(r[3]) : "r"(addr));
}
__device__ __forceinline__ void mma16816(float* c, const uint32_t* a,
                                         uint32_t b0, uint32_t b1) {
    asm volatile("mma.sync.aligned.m16n8k16.row.col.f32.f16.f16.f32 "
                 "{%0,%1,%2,%3}, {%4,%5,%6,%7}, {%8,%9}, {%0,%1,%2,%3};"
                 : "+f"(c[0]), "+f"(c[1]), "+f"(c[2]), "+f"(c[3])
                 : "r"(a[0]), "r"(a[1]), "r"(a[2]), "r"(a[3]), "r"(b0), "r"(b1));
}

// ---------------- tensor-core dual GEMM body ----------------------------------
// Warps 0-3: P0[i,c] = (h@W0)[i,c] + b[c]  (fp32)
// Warps 4-7: Zh[i,c] = fp16((h@W1)[i,c])
// HIN=false: fp32 H + fp32 weights (layer 0). HIN=true: fp16 H + fp16 weights.
template<int COUT, int NTP, bool RELU, bool HIN>
__device__ __forceinline__
void gemm_body16(int gblk,
                 const float* __restrict__ Xf,
                 const __half* __restrict__ Hh,
                 const float* __restrict__ W0f,
                 const float* __restrict__ W1f,
                 const __half* __restrict__ Wh,
                 const float* __restrict__ B,
                 float* __restrict__ P0,
                 __half* __restrict__ Zh)
{
    // alignas(16) is load-bearing — ldmatrix requires 16B-aligned addresses.
    __shared__ alignas(16) __half sH[64][72];
    __shared__ alignas(16) __half sW[2][64][72];
    const int t    = threadIdx.x;
    const int row0 = gblk * 64;

    if (HIN) {
        // fp16 weights: pure uint4 copies (2 mats x 64x64 halves = 1024 uint4)
        #pragma unroll
        for (int j = 0; j < 4; j++) {
            int elem = (t + j * 256) * 8;           // half index, 0..8191
            int mat  = elem >> 12;
            int rem  = elem & 4095;
            int k    = rem >> 6, c = rem & 63;
            uint4 v = *reinterpret_cast<const uint4*>(Wh + mat * 4096 + k * 64 + c);
            *reinterpret_cast<uint4*>(&sW[mat][k][c]) = v;
        }
        // fp16 H tile: 64 rows x 128B = 512 uint4; optional relu via hmax2
        const __half2 z2 = __floats2half2_rn(0.f, 0.f);
        #pragma unroll
        for (int j = 0; j < 2; j++) {
            int r = (t >> 3) + j * 32, sg = (t & 7) * 8;
            int gr = row0 + r;
            uint4 v = make_uint4(0u, 0u, 0u, 0u);
            if (gr < N_NODES) v = *reinterpret_cast<const uint4*>(Hh + (size_t)gr * 64 + sg);
            if (RELU) {
                __half2* h = reinterpret_cast<__half2*>(&v);
                h[0] = __hmax2(h[0], z2); h[1] = __hmax2(h[1], z2);
                h[2] = __hmax2(h[2], z2); h[3] = __hmax2(h[3], z2);
            }
            *reinterpret_cast<uint4*>(&sH[r][sg]) = v;
        }
    } else {
        for (int i = t; i < 4096; i += 256) {
            int k = i >> 6, c = i & 63;
            float w0 = 0.f, w1 = 0.f;
            if (c < COUT) { w0 = W0f[k * COUT + c]; w1 = W1f[k * COUT + c]; }
            sW[0][k][c] = __float2half(w0);
            sW[1][k][c] = __float2half(w1);
        }
        for (int i = t; i < 1024; i += 256) {
            int r = i >> 4, c = (i & 15) * 4;
            int gr = row0 + r;
            float4 v = make_float4(0.f, 0.f, 0.f, 0.f);
            if (gr < N_NODES) v = *reinterpret_cast<const float4*>(Xf + (size_t)gr * 64 + c);
            *reinterpret_cast<__half2*>(&sH[r][c])     = __floats2half2_rn(v.x, v.y);
            *reinterpret_cast<__half2*>(&sH[r][c + 2]) = __floats2half2_rn(v.z, v.w);
        }
    }
    __syncthreads();

    const int lane = t & 31, wid = t >> 5;
    const int mat = wid >> 2;              // 0 -> W0/P0, 1 -> W1/Zh
    const int mrow = (wid & 3) * 16;       // 16 M-rows per warp
    float acc[2 * NTP][4];
    #pragma unroll
    for (int i = 0; i < 2 * NTP; i++) { acc[i][0] = acc[i][1] = acc[i][2] = acc[i][3] = 0.f; }

    const int arow  = mrow + (lane & 15);
    const int ahalf = (lane >> 4) * 8;
    const int krow  = (lane & 7) + ((lane >> 3) & 1) * 8;
    const int ncOff = (lane >> 4) * 8;

    #pragma unroll
    for (int kk = 0; kk < 4; kk++) {
        uint32_t a[4];
        ldsm_x4(a, smem_u32(&sH[arow][kk * 16 + ahalf]));
        #pragma unroll
        for (int p = 0; p < NTP; p++) {
            uint32_t b4[4];
            ldsm_x4t(b4, smem_u32(&sW[mat][kk * 16 + krow][p * 16 + ncOff]));
            mma16816(acc[2 * p],     a, b4[0], b4[1]);
            mma16816(acc[2 * p + 1], a, b4[2], b4[3]);
        }
    }

    const int g   = lane >> 2;
    const int cp  = (lane & 3) * 2;
    const int gr0 = row0 + mrow + g;
    const int gr1 = gr0 + 8;
    if (mat == 0) {
        #pragma unroll
        for (int nt = 0; nt < 2 * NTP; nt++) {
            int gc = nt * 8 + cp;
            if (gc >= COUT) continue;
            float b0 = __ldg(B + gc), b1 = __ldg(B + gc + 1);
            if (gr0 < N_NODES)
                *reinterpret_cast<float2*>(P0 + (size_t)gr0 * 64 + gc) =
                    make_float2(acc[nt][0] + b0, acc[nt][1] + b1);
            if (gr1 < N_NODES)
                *reinterpret_cast<float2*>(P0 + (size_t)gr1 * 64 + gc) =
                    make_float2(acc[nt][2] + b0, acc[nt][3] + b1);
        }
    } else {
        #pragma unroll
        for (int nt = 0; nt < 2 * NTP; nt++) {
            int gc = nt * 8 + cp;
            if (gc >= COUT) continue;
            if (gr0 < N_NODES) {
                __half2 h = __floats2half2_rn(acc[nt][0], acc[nt][1]);
                *reinterpret_cast<__half2*>(Zh + (size_t)gr0 * 64 + gc) = h;
            }
            if (gr1 < N_NODES) {
                __half2 h = __floats2half2_rn(acc[nt][2], acc[nt][3]);
                *reinterpret_cast<__half2*>(Zh + (size_t)gr1 * 64 + gc) = h;
            }
        }
    }
}

// ---------------- prologue kernels --------------------------------------------
// roles: degree counting (4:1) | layer-0 GEMM | 2 weight-conversion blocks
__global__ __launch_bounds__(256)
void k_combo(const int* __restrict__ esrc, const int* __restrict__ edst,
             const float* __restrict__ X,
             const float* __restrict__ W0, const float* __restrict__ W1,
             const float* __restrict__ B,
             const float* __restrict__ W0_1, const float* __restrict__ W1_1,
             const float* __restrict__ W0_2, const float* __restrict__ W1_2,
             float* __restrict__ P0, __half* __restrict__ Zh)
{
    int bid = blockIdx.x;
    if (bid >= NB_COMBO) {
        int t = threadIdx.x;
        if (bid == NB_COMBO) {
            // layer-1 weights -> fp16 (2 x 64x64)
            for (int i = t; i < 8192; i += 256) {
                int mat = i >> 12, rem = i & 4095;
                const float* src = mat ? W1_1 : W0_1;
                g_w1h[i] = __float2half(src[rem]);
            }
        } else {
            // layer-2 weights -> fp16, zero-padded 40 -> 64 cols
            for (int i = t; i < 8192; i += 256) {
                int mat = i >> 12, rem = i & 4095;
                int k = rem >> 6, c = rem & 63;
                const float* src = mat ? W1_2 : W0_2;
                g_w2h[i] = __float2half(c < 40 ? src[k * 40 + c] : 0.f);
            }
        }
        return;
    }
    int q = bid / 5, r = bid - q * 5;
    if (r == 4) {
        gemm_body16<64, 4, false, false>(q, X, nullptr, W0, W1, nullptr, B, P0, Zh);
    } else {
        int degIdx = bid - q;
        int e = degIdx * 256 + threadIdx.x;
        if (e < E_EDGES) {
            atomicAdd(&g_deg_src[esrc[e]], 1);
            atomicAdd(&g_deg_dst[edst[e]], 1);
        }
    }
}

// exclusive scan of deg_dst (chunk-local pass) + max-reduce of deg_src
__global__ __launch_bounds__(256) void k_scan1()
{
    __shared__ int warp_tot[8];
    __shared__ int warp_max[8];
    int b = blockIdx.x, t = threadIdx.x;
    int base = b * SCAN_CHUNK + t * 4;
    int v0 = (base + 0 < N_NODES) ? g_deg_dst[base + 0] : 0;
    int v1 = (base + 1 < N_NODES) ? g_deg_dst[base + 1] : 0;
    int v2 = (base + 2 < N_NODES) ? g_deg_dst[base + 2] : 0;
    int v3 = (base + 3 < N_NODES) ? g_deg_dst[base + 3] : 0;
    int m0 = (base + 0 < N_NODES) ? g_deg_src[base + 0] : 0;
    int m1 = (base + 1 < N_NODES) ? g_deg_src[base + 1] : 0;
    int m2 = (base + 2 < N_NODES) ? g_deg_src[base + 2] : 0;
    int m3 = (base + 3 < N_NODES) ? g_deg_src[base + 3] : 0;
    int s1 = v0, s2 = s1 + v1, s3 = s2 + v2, tot = s3 + v3;
    int mx = max(max(m0, m1), max(m2, m3));

    int lane = t & 31, w = t >> 5;
    int inc = tot;
    #pragma unroll
    for (int o = 1; o < 32; o <<= 1) {
        int n = __shfl_up_sync(0xFFFFFFFFu, inc, o);
        if (lane >= o) inc += n;
    }
    #pragma unroll
    for (int o = 16; o; o >>= 1) mx = max(mx, __shfl_xor_sync(0xFFFFFFFFu, mx, o));
    if (lane == 31) warp_tot[w] = inc;
    if (lane == 0)  warp_max[w] = mx;
    __syncthreads();
    if (t == 0) {
        int run = 0, bm = 0;
        #pragma unroll
        for (int i = 0; i < 8; i++) {
            int x = warp_tot[i]; warp_tot[i] = run; run += x;
            bm = max(bm, warp_max[i]);
        }
        g_blockSums[b] = run;
        atomicMax(&g_maxdeg, bm);
    }
    __syncthreads();
    int excl = warp_tot[w] + (inc - tot);
    if (base + 0 < N_NODES) g_row_start[base + 0] = excl;
    if (base + 1 < N_NODES) g_row_start[base + 1] = excl + s1;
    if (base + 2 < N_NODES) g_row_start[base + 2] = excl + s2;
    if (base + 3 < N_NODES) g_row_start[base + 3] = excl + s3;
}

// finalize row_start: parallel scan of the 98 chunk sums (redundant per block)
__global__ __launch_bounds__(256) void k_scan3()
{
    __shared__ int soff[128];
    int t = threadIdx.x;
    if (t < 128) soff[t] = (t < NB_SCAN) ? g_blockSums[t] : 0;
    __syncthreads();
    #pragma unroll
    for (int o = 1; o < 128; o <<= 1) {
        int v = 0;
        if (t < 128 && t >= o) v = soff[t - o];
        __syncthreads();
        if (t < 128) soff[t] += v;
        __syncthreads();
    }
    int i = blockIdx.x * 256 + t;
    if (i < N_NODES) {
        int c = i >> 10;
        int off = (c == 0) ? 0 : soff[c - 1];
        int rs = g_row_start[i] + off;
        g_row_start[i] = rs;
        g_cursor[i] = rs;
    }
    if (i == 0) {
        g_row_start[N_NODES] = E_EDGES;
        g_scale = 1.0f / (float)max(g_maxdeg, 1);
    }
}

// CSR fill; also restores zero-invariant for deg_dst and maxdeg (read is done)
__global__ void k_fill(const int* __restrict__ esrc, const int* __restrict__ edst)
{
    int e = blockIdx.x * blockDim.x + threadIdx.x;
    if (e < N_NODES) g_deg_dst[e] = 0;
    if (e == 0) g_maxdeg = 0;
    if (e < E_EDGES) {
        int d = edst[e];
        int pos = atomicAdd(&g_cursor[d], 1);
        g_csr_src[pos] = esrc[e];
    }
}

// ---------------- standalone tensor-core GEMM kernels (layers 1, 2) -----------
template<int COUT, int NTP>
__global__ __launch_bounds__(256)
void cheb_gemm16(const __half* __restrict__ H,
                 const __half* __restrict__ Wh,
                 const float* __restrict__ B,
                 float* __restrict__ P0, __half* __restrict__ Zh)
{
    gemm_body16<COUT, NTP, true, true>(blockIdx.x, nullptr, H, nullptr, nullptr,
                                       Wh, B, P0, Zh);
}

// ---------------- CSR gather: half-warp (16 lanes) per node -------------------
// Hout[i] = fp16( P0[i] + (deg_src[i]*scale - 1)*z[i] - scale*sum_{in(i)} z[src] )
// (pre-relu; relu applied on the next GEMM's tile load)
__global__ __launch_bounds__(256)
void cheb_gather64(const float* __restrict__ P0,
                   const __half* __restrict__ Zh,
                   __half* __restrict__ Hout)
{
    int grp = (blockIdx.x * blockDim.x + threadIdx.x) >> 4;  // node id
    int c4  = threadIdx.x & 15;                              // channel quad
    if (grp >= N_NODES) return;
    const uint2* Zv = reinterpret_cast<const uint2*>(Zh);    // 16 uint2 per row

    int beg = g_row_start[grp], end = g_row_start[grp + 1];
    float4 acc = make_float4(0.f, 0.f, 0.f, 0.f);
    int e = beg;
    #pragma unroll 1
    for (; e + 4 <= end; e += 4) {
        #pragma unroll
        for (int u = 0; u < 4; u++) {
            int s = __ldg(&g_csr_src[e + u]);
            uint2 d = __ldg(Zv + (size_t)s * 16 + c4);
            __half2 h0 = *reinterpret_cast<__half2*>(&d.x);
            __half2 h1 = *reinterpret_cast<__half2*>(&d.y);
            float2 f0 = __half22float2(h0), f1 = __half22float2(h1);
            acc.x += f0.x; acc.y += f0.y; acc.z += f1.x; acc.w += f1.y;
        }
    }
    for (; e < end; e++) {
        int s = __ldg(&g_csr_src[e]);
        uint2 d = __ldg(Zv + (size_t)s * 16 + c4);
        __half2 h0 = *reinterpret_cast<__half2*>(&d.x);
        __half2 h1 = *reinterpret_cast<__half2*>(&d.y);
        float2 f0 = __half22float2(h0), f1 = __half22float2(h1);
        acc.x += f0.x; acc.y += f0.y; acc.z += f1.x; acc.w += f1.y;
    }

    float scale = g_scale;
    float nl = (float)__ldg(&g_deg_src[grp]) * scale - 1.0f;
    uint2 dz = __ldg(Zv + (size_t)grp * 16 + c4);
    __half2 z0h = *reinterpret_cast<__half2*>(&dz.x);
    __half2 z1h = *reinterpret_cast<__half2*>(&dz.y);
    float2 z0 = __half22float2(z0h), z1 = __half22float2(z1h);
    float4 p = __ldg(reinterpret_cast<const float4*>(P0 + (size_t)grp * 64) + c4);
    float4 o;
    o.x = p.x + nl * z0.x - scale * acc.x;
    o.y = p.y + nl * z0.y - scale * acc.y;
    o.z = p.z + nl * z1.x - scale * acc.z;
    o.w = p.w + nl * z1.y - scale * acc.w;
    __half2 q0 = __floats2half2_rn(o.x, o.y);
    __half2 q1 = __floats2half2_rn(o.z, o.w);
    uint2 st;
    st.x = *reinterpret_cast<unsigned*>(&q0);
    st.y = *reinterpret_cast<unsigned*>(&q1);
    *reinterpret_cast<uint2*>(Hout + (size_t)grp * 64 + c4 * 4) = st;
}

// ---------------- final: gather (40 ch) + log_softmax; resets deg_src ---------
__global__ __launch_bounds__(256)
void cheb_gather40_lsm(const float* __restrict__ P0,
                       const __half* __restrict__ Zh,
                       float* __restrict__ out)
{
    int warp = (blockIdx.x * blockDim.x + threadIdx.x) >> 5;
    int lane = threadIdx.x & 31;
    if (warp >= N_NODES) return;
    const __half2* Z2 = reinterpret_cast<const __half2*>(Zh);
    int beg = g_row_start[warp], end = g_row_start[warp + 1];
    float2 acc = make_float2(0.f, 0.f);
    bool act = lane < 20;
    int e = beg;
    for (; e + 4 <= end; e += 4) {
        int s0 = __ldg(&g_csr_src[e + 0]);
        int s1 = __ldg(&g_csr_src[e + 1]);
        int s2 = __ldg(&g_csr_src[e + 2]);
        int s3 = __ldg(&g_csr_src[e + 3]);
        if (act) {
            float2 f0 = __half22float2(__ldg(Z2 + (size_t)s0 * 32 + lane));
            float2 f1 = __half22float2(__ldg(Z2 + (size_t)s1 * 32 + lane));
            float2 f2 = __half22float2(__ldg(Z2 + (size_t)s2 * 32 + lane));
            float2 f3 = __half22float2(__ldg(Z2 + (size_t)s3 * 32 + lane));
            acc.x += (f0.x + f1.x) + (f2.x + f3.x);
            acc.y += (f0.y + f1.y) + (f2.y + f3.y);
        }
    }
    for (; e < end; e++) {
        int s = __ldg(&g_csr_src[e]);
        if (act) {
            float2 f = __half22float2(__ldg(Z2 + (size_t)s * 32 + lane));
            acc.x += f.x; acc.y += f.y;
        }
    }
    float v0 = -3.0e38f, v1 = -3.0e38f;
    if (act) {
        float scale = g_scale;
        float nl = (float)__ldg(&g_deg_src[warp]) * scale - 1.0f;
        float2 zs = __half22float2(__ldg(Z2 + (size_t)warp * 32 + lane));
        float2 p = *reinterpret_cast<const float2*>(P0 + (size_t)warp * 64 + 2 * lane);
        v0 = p.x + nl * zs.x - scale * acc.x;
        v1 = p.y + nl * zs.y - scale * acc.y;
    }
    float m = fmaxf(v0, v1);
    #pragma unroll
    for (int o = 16; o; o >>= 1) m = fmaxf(m, __shfl_xor_sync(0xFFFFFFFFu, m, o));
    float s = act ? (expf(v0 - m) + expf(v1 - m)) : 0.f;
    #pragma unroll
    for (int o = 16; o; o >>= 1) s += __shfl_xor_sync(0xFFFFFFFFu, s, o);
    float ls = m + logf(s);
    if (act) {
        float2 o2 = make_float2(v0 - ls, v1 - ls);
        *reinterpret_cast<float2*>(out + (size_t)warp * 40 + 2 * lane) = o2;
    }
    // restore zero-invariant for next call (all reads of deg_src are done)
    __syncwarp();
    if (lane == 0) g_deg_src[warp] = 0;
}

// ---------------- launch ------------------------------------------------------
extern "C" void kernel_launch(void* const* d_in, const int* in_sizes, int n_in,
                              void* d_out, int out_size)
{
    const float* x    = (const float*)d_in[0];
    const int*   ei   = (const int*)d_in[1];
    const int*   esrc = ei;
    const int*   edst = ei + E_EDGES;
    const float* W0_0 = (const float*)d_in[2];
    const float* W1_0 = (const float*)d_in[3];
    const float* b_0  = (const float*)d_in[4];
    const float* W0_1 = (const float*)d_in[5];
    const float* W1_1 = (const float*)d_in[6];
    const float* b_1  = (const float*)d_in[7];
    const float* W0_2 = (const float*)d_in[8];
    const float* W1_2 = (const float*)d_in[9];
    const float* b_2  = (const float*)d_in[10];

    float  *bufP0;
    __half *bufZ0, *bufH, *w1h, *w2h;
    cudaGetSymbolAddress((void**)&bufP0, g_bufP0);
    cudaGetSymbolAddress((void**)&bufZ0, g_bufZ0);
    cudaGetSymbolAddress((void**)&bufH,  g_bufH);
    cudaGetSymbolAddress((void**)&w1h,   g_w1h);
    cudaGetSymbolAddress((void**)&w2h,   g_w2h);

    const int NB_N  = (N_NODES + 255) / 256;         // 391
    const int NB_W  = (N_NODES * 32 + 255) / 256;    // 12500 (warp/node)
    const int NB_HW = (N_NODES * 16 + 255) / 256;    // 6250  (half-warp/node)

    // prologue: deg count + layer-0 GEMM + weight conversion, then scan + fill
    k_combo<<<NB_COMBO + 2, 256>>>(esrc, edst, x, W0_0, W1_0, b_0,
                                   W0_1, W1_1, W0_2, W1_2, bufP0, bufZ0);
    k_scan1<<<NB_SCAN, 256>>>();
    k_scan3<<<NB_N, 256>>>();
    k_fill<<<NB_E, 256>>>(esrc, edst);

    // Layer 0 aggregate -> H1 (fp16, pre-relu)
    cheb_gather64<<<NB_HW, 256>>>(bufP0, bufZ0, bufH);
    // Layer 1 (tensor cores, fp16 in; relu on load)
    cheb_gemm16<64, 4><<<NB_G, 256>>>(bufH, w1h, b_1, bufP0, bufZ0);
    cheb_gather64<<<NB_HW, 256>>>(bufP0, bufZ0, bufH);
    // Layer 2 (tensor cores, 40 cols -> 3 n-tile pairs; relu on load)
    cheb_gemm16<40, 3><<<NB_G, 256>>>(bufH, w2h, b_2, bufP0, bufZ0);
    // Final aggregate + log_softmax (also resets deg_src invariant)
    cheb_gather40_lsm<<<NB_W, 256>>>(bufP0, bufZ0, (float*)d_out);
}